// round 1
// baseline (speedup 1.0000x reference)
#include <cuda_runtime.h>
#include <cuda_bf16.h>
#include <cstdint>

// Problem constants
#define BATCH 8
#define SEQ   4096
#define DM    1024
#define NH    16
#define NG    4
#define HD    64
#define HG    (NH*NG)          // 64
#define MROWS (BATCH*SEQ)      // 32768
#define INV_SCALE 0.125f       // 1/sqrt(64)

// ---------------------------------------------------------------------------
// Scratch (device globals: allocation-free per harness rules)
// ---------------------------------------------------------------------------
__device__ float g_q [MROWS * DM];   // q  (kept to the end: final +q)
__device__ float g_k [MROWS * DM];   // k
__device__ float g_v [MROWS * DM];   // v
__device__ float g_t [MROWS * DM];   // qk, then u (reused)
__device__ float g_s1[MROWS * HG];   // q scores -> qw (softmax)
__device__ float g_s2[MROWS * HG];   // k scores (ksc, no softmax)
__device__ float g_gq[BATCH * NH * HD * NG];
__device__ float g_gk[BATCH * NH * HD * NG];

// ---------------------------------------------------------------------------
// Big SGEMM: C[M,N] = A[M,K] @ W[K,N] + bias (+ add).  128x128x8 tile,
// 256 threads, 8x8 per-thread register tile, fp32.
// ---------------------------------------------------------------------------
__global__ __launch_bounds__(256) void sgemm_big(
    const float* __restrict__ A, const float* __restrict__ W,
    const float* __restrict__ bias, const float* __restrict__ addv,
    float* __restrict__ C, int Kdim, int Ndim)
{
    __shared__ __align__(16) float As[8][128];
    __shared__ __align__(16) float Bs[8][128];

    const int tid  = threadIdx.x;
    const int brow = blockIdx.y * 128;
    const int bcol = blockIdx.x * 128;

    // A tile load: row = tid/2 (0..127), k offset = (tid&1)*4 -> one float4
    const int arow = tid >> 1;
    const int akof = (tid & 1) * 4;
    // B tile load: k row = tid/32 (0..7), col = (tid&31)*4 -> one float4
    const int bkr  = tid >> 5;
    const int bc4  = (tid & 31) * 4;

    const int trow = (tid >> 4) * 8;   // 0..120
    const int tcol = (tid & 15) * 8;   // 0..120

    float acc[8][8];
    #pragma unroll
    for (int i = 0; i < 8; i++)
        #pragma unroll
        for (int j = 0; j < 8; j++) acc[i][j] = 0.f;

    const float* Ab = A + (size_t)(brow + arow) * Kdim + akof;
    const float* Wb = W + (size_t)bkr * Ndim + bcol + bc4;

    for (int k0 = 0; k0 < Kdim; k0 += 8) {
        float4 av = *(const float4*)(Ab + k0);
        As[akof + 0][arow] = av.x;
        As[akof + 1][arow] = av.y;
        As[akof + 2][arow] = av.z;
        As[akof + 3][arow] = av.w;
        float4 bv = *(const float4*)(Wb + (size_t)k0 * Ndim);
        *(float4*)&Bs[bkr][bc4] = bv;
        __syncthreads();

        #pragma unroll
        for (int kk = 0; kk < 8; kk++) {
            float4 a0 = *(const float4*)&As[kk][trow];
            float4 a1 = *(const float4*)&As[kk][trow + 4];
            float4 b0 = *(const float4*)&Bs[kk][tcol];
            float4 b1 = *(const float4*)&Bs[kk][tcol + 4];
            float ar[8] = {a0.x,a0.y,a0.z,a0.w,a1.x,a1.y,a1.z,a1.w};
            float br[8] = {b0.x,b0.y,b0.z,b0.w,b1.x,b1.y,b1.z,b1.w};
            #pragma unroll
            for (int i = 0; i < 8; i++)
                #pragma unroll
                for (int j = 0; j < 8; j++)
                    acc[i][j] = fmaf(ar[i], br[j], acc[i][j]);
        }
        __syncthreads();
    }

    #pragma unroll
    for (int i = 0; i < 8; i++) {
        const size_t row = (size_t)(brow + trow + i);
        float* crow = C + row * Ndim + bcol + tcol;
        const float* arow_ = addv ? (addv + row * Ndim + bcol + tcol) : nullptr;
        #pragma unroll
        for (int j = 0; j < 8; j++) {
            float val = acc[i][j] + bias[bcol + tcol + j];
            if (arow_) val += arow_[j];
            crow[j] = val;
        }
    }
}

// ---------------------------------------------------------------------------
// Small SGEMM: C[M,64] = A[M,1024] @ W[1024,64] + bias, optional fused
// (val * 1/8 + mask[row]).  64x64x16 tile, 256 threads, 4x4 per thread.
// ---------------------------------------------------------------------------
__global__ __launch_bounds__(256) void sgemm_small(
    const float* __restrict__ A, const float* __restrict__ W,
    const float* __restrict__ bias, const float* __restrict__ mask,
    float* __restrict__ C, int Kdim)
{
    __shared__ __align__(16) float As[16][64];
    __shared__ __align__(16) float Bs[16][64];

    const int tid  = threadIdx.x;
    const int brow = blockIdx.y * 64;

    const int arow = tid >> 2;          // 0..63
    const int akof = (tid & 3) * 4;     // 0,4,8,12
    const int bkr  = tid >> 4;          // 0..15
    const int bc4  = (tid & 15) * 4;    // 0..60

    const int trow = (tid >> 4) * 4;    // 0..60
    const int tcol = (tid & 15) * 4;    // 0..60

    float acc[4][4];
    #pragma unroll
    for (int i = 0; i < 4; i++)
        #pragma unroll
        for (int j = 0; j < 4; j++) acc[i][j] = 0.f;

    const float* Ab = A + (size_t)(brow + arow) * Kdim + akof;
    const float* Wb = W + (size_t)bkr * HG + bc4;

    for (int k0 = 0; k0 < Kdim; k0 += 16) {
        float4 av = *(const float4*)(Ab + k0);
        As[akof + 0][arow] = av.x;
        As[akof + 1][arow] = av.y;
        As[akof + 2][arow] = av.z;
        As[akof + 3][arow] = av.w;
        float4 bv = *(const float4*)(Wb + (size_t)k0 * HG);
        *(float4*)&Bs[bkr][bc4] = bv;
        __syncthreads();

        #pragma unroll
        for (int kk = 0; kk < 16; kk++) {
            float4 a0 = *(const float4*)&As[kk][trow];
            float4 b0 = *(const float4*)&Bs[kk][tcol];
            float ar[4] = {a0.x,a0.y,a0.z,a0.w};
            float br[4] = {b0.x,b0.y,b0.z,b0.w};
            #pragma unroll
            for (int i = 0; i < 4; i++)
                #pragma unroll
                for (int j = 0; j < 4; j++)
                    acc[i][j] = fmaf(ar[i], br[j], acc[i][j]);
        }
        __syncthreads();
    }

    #pragma unroll
    for (int i = 0; i < 4; i++) {
        const int row = brow + trow + i;
        const float mval = mask ? mask[row] : 0.f;
        #pragma unroll
        for (int j = 0; j < 4; j++) {
            float val = acc[i][j] + bias[tcol + j];
            if (mask) val = val * INV_SCALE + mval;
            C[(size_t)row * HG + tcol + j] = val;
        }
    }
}

// ---------------------------------------------------------------------------
// Softmax over n (=SEQ) for each (b, col) column of s[M, HG].
// Applies (v/8 + mask) before softmax. One block per (b, col), 256 threads,
// 16 values registered per thread.
// ---------------------------------------------------------------------------
__global__ __launch_bounds__(256) void softmax_n(
    float* __restrict__ s, const float* __restrict__ mask)
{
    const int b   = blockIdx.x / HG;
    const int col = blockIdx.x % HG;
    const int tid = threadIdx.x;

    float* base = s + (size_t)b * SEQ * HG + col;
    const float* mb = mask + (size_t)b * SEQ;

    float vals[16];
    float mx = -1e30f;
    #pragma unroll
    for (int i = 0; i < 16; i++) {
        const int n = tid + i * 256;
        float v = base[(size_t)n * HG] * INV_SCALE + mb[n];
        vals[i] = v;
        mx = fmaxf(mx, v);
    }

    __shared__ float red[256];
    red[tid] = mx; __syncthreads();
    for (int st = 128; st > 0; st >>= 1) {
        if (tid < st) red[tid] = fmaxf(red[tid], red[tid + st]);
        __syncthreads();
    }
    mx = red[0]; __syncthreads();

    float sum = 0.f;
    #pragma unroll
    for (int i = 0; i < 16; i++) {
        vals[i] = __expf(vals[i] - mx);
        sum += vals[i];
    }
    red[tid] = sum; __syncthreads();
    for (int st = 128; st > 0; st >>= 1) {
        if (tid < st) red[tid] += red[tid + st];
        __syncthreads();
    }
    const float rs = 1.f / red[0];

    #pragma unroll
    for (int i = 0; i < 16; i++) {
        const int n = tid + i * 256;
        base[(size_t)n * HG] = vals[i] * rs;
    }
}

// ---------------------------------------------------------------------------
// g[b,h,d,g] = sum_n w[b,n,h,g] * x[b,n,h*64+d].  One block per (b,h),
// 256 threads = (g,d) pairs, tid = g*64 + d.
// ---------------------------------------------------------------------------
__global__ __launch_bounds__(256) void gsum_k(
    const float* __restrict__ x, const float* __restrict__ w,
    float* __restrict__ out)
{
    const int b = blockIdx.x / NH;
    const int h = blockIdx.x % NH;
    const int g = threadIdx.x >> 6;
    const int d = threadIdx.x & 63;

    const float* xp = x + (size_t)b * SEQ * DM + h * HD + d;
    const float* wp = w + (size_t)b * SEQ * HG + h * NG + g;

    float a0 = 0.f, a1 = 0.f, a2 = 0.f, a3 = 0.f;
    for (int n = 0; n < SEQ; n += 4) {
        a0 = fmaf(xp[(size_t)(n + 0) * DM], wp[(size_t)(n + 0) * HG], a0);
        a1 = fmaf(xp[(size_t)(n + 1) * DM], wp[(size_t)(n + 1) * HG], a1);
        a2 = fmaf(xp[(size_t)(n + 2) * DM], wp[(size_t)(n + 2) * HG], a2);
        a3 = fmaf(xp[(size_t)(n + 3) * DM], wp[(size_t)(n + 3) * HG], a3);
    }
    out[(((size_t)(b * NH + h) * HD) + d) * NG + g] = (a0 + a1) + (a2 + a3);
}

// ---------------------------------------------------------------------------
// out[m, hd] = max_g x[m, hd] * gm[b, h, d, g]
// ---------------------------------------------------------------------------
__global__ __launch_bounds__(256) void maxg_k(
    const float* __restrict__ x, const float* __restrict__ gm,
    float* __restrict__ out)
{
    const size_t i = (size_t)blockIdx.x * 256 + threadIdx.x;
    const int hd = (int)(i & (DM - 1));
    const size_t m = i >> 10;            // / DM
    const int b = (int)(m >> 12);        // / SEQ
    const int h = hd >> 6;
    const int d = hd & 63;

    const float4 gv = *(const float4*)&gm[(((size_t)(b * NH + h) * HD) + d) * NG];
    const float xv = x[i];
    out[i] = fmaxf(fmaxf(xv * gv.x, xv * gv.y), fmaxf(xv * gv.z, xv * gv.w));
}

// ---------------------------------------------------------------------------
// Launch
// ---------------------------------------------------------------------------
extern "C" void kernel_launch(void* const* d_in, const int* in_sizes, int n_in,
                              void* d_out, int out_size)
{
    const float* hs   = (const float*)d_in[0];
    const float* mask = (const float*)d_in[1];
    const float* Wq   = (const float*)d_in[2];
    const float* bq   = (const float*)d_in[3];
    const float* Wqa  = (const float*)d_in[4];
    const float* bqa  = (const float*)d_in[5];
    const float* Wk   = (const float*)d_in[6];
    const float* bk   = (const float*)d_in[7];
    const float* Wka  = (const float*)d_in[8];
    const float* bka  = (const float*)d_in[9];
    const float* Wv   = (const float*)d_in[10];
    const float* bv   = (const float*)d_in[11];
    const float* Wt   = (const float*)d_in[12];
    const float* bt   = (const float*)d_in[13];
    float* out = (float*)d_out;

    float *q, *k, *v, *t, *s1, *s2, *gq, *gk;
    cudaGetSymbolAddress((void**)&q,  g_q);
    cudaGetSymbolAddress((void**)&k,  g_k);
    cudaGetSymbolAddress((void**)&v,  g_v);
    cudaGetSymbolAddress((void**)&t,  g_t);
    cudaGetSymbolAddress((void**)&s1, g_s1);
    cudaGetSymbolAddress((void**)&s2, g_s2);
    cudaGetSymbolAddress((void**)&gq, g_gq);
    cudaGetSymbolAddress((void**)&gk, g_gk);

    dim3 gBig(DM / 128, MROWS / 128);       // (8, 256)
    dim3 gSmall(1, MROWS / 64);             // (1, 512)

    // 1-3. q, k, v projections
    sgemm_big<<<gBig, 256>>>(hs, Wq, bq, nullptr, q, DM, DM);
    sgemm_big<<<gBig, 256>>>(hs, Wk, bk, nullptr, k, DM, DM);
    sgemm_big<<<gBig, 256>>>(hs, Wv, bv, nullptr, v, DM, DM);

    // 4. raw q scores -> s1   (scale+mask applied inside softmax)
    sgemm_small<<<gSmall, 256>>>(q, Wqa, bqa, nullptr, s1, DM);

    // 5. softmax over n per (b, h, g)
    softmax_n<<<BATCH * HG, 256>>>(s1, mask);

    // 6. gq[b,h,d,g] = sum_n qw * q
    gsum_k<<<BATCH * NH, 256>>>(q, s1, gq);

    // 7. qk[m,hd] = max_g k * gq   (into t)
    maxg_k<<<(MROWS * DM) / 256, 256>>>(k, gq, t);

    // 8. ksc = (qk @ Wka + bka)/8 + mask  -> s2 (fused epilogue, no softmax)
    sgemm_small<<<gSmall, 256>>>(t, Wka, bka, mask, s2, DM);

    // 9. gk[b,h,d,g] = sum_n ksc * k
    gsum_k<<<BATCH * NH, 256>>>(k, s2, gk);

    // 10. u[m,hd] = max_g v * gk   (reuse t)
    maxg_k<<<(MROWS * DM) / 256, 256>>>(v, gk, t);

    // 11. out = u @ Wt + bt + q
    sgemm_big<<<gBig, 256>>>(t, Wt, bt, q, out, DM, DM);
}

// round 3
// speedup vs baseline: 1.8060x; 1.8060x over previous
#include <cuda_runtime.h>
#include <cuda_bf16.h>
#include <cstdint>

// Problem constants
#define BATCH 8
#define SEQ   4096
#define DM    1024
#define NH    16
#define NG    4
#define HD    64
#define HG    (NH*NG)          // 64
#define MROWS (BATCH*SEQ)      // 32768
#define INV_SCALE 0.125f       // 1/sqrt(64)

// ---------------------------------------------------------------------------
// Scratch (device globals: allocation-free per harness rules)
// ---------------------------------------------------------------------------
__device__ float g_q [MROWS * DM];
__device__ float g_k [MROWS * DM];
__device__ float g_v [MROWS * DM];
__device__ float g_t [MROWS * DM];
__device__ float g_s1[MROWS * HG];
__device__ float g_s2[MROWS * HG];
__device__ float g_gq[BATCH * NH * HD * NG];
__device__ float g_gk[BATCH * NH * HD * NG];
// bf16 split buffers (A operand: hs, then u)
__device__ __align__(256) __nv_bfloat16 g_ah[MROWS * DM];
__device__ __align__(256) __nv_bfloat16 g_al[MROWS * DM];
// transposed + split weights [N][K] bf16
__device__ __align__(256) __nv_bfloat16 g_wh[4][DM * DM];
__device__ __align__(256) __nv_bfloat16 g_wl[4][DM * DM];

// ---------------------------------------------------------------------------
// PTX helpers (plain sm_103-safe: mma.sync / ldmatrix / cp.async only)
// ---------------------------------------------------------------------------
__device__ __forceinline__ uint32_t smem_u32(const void* p) {
    uint32_t a;
    asm("{ .reg .u64 t; cvta.to.shared.u64 t, %1; cvt.u32.u64 %0, t; }"
        : "=r"(a) : "l"(p));
    return a;
}
#define CP_ASYNC16(s, g) \
    asm volatile("cp.async.cg.shared.global [%0], [%1], 16;" :: "r"(s), "l"(g))
#define CP_COMMIT() asm volatile("cp.async.commit_group;" ::: "memory")
#define CP_WAIT(n)  asm volatile("cp.async.wait_group %0;" :: "n"(n) : "memory")
#define LDMX4(r, addr) \
    asm volatile("ldmatrix.sync.aligned.m8n8.x4.shared.b16 {%0,%1,%2,%3}, [%4];" \
        : "=r"((r)[0]), "=r"((r)[1]), "=r"((r)[2]), "=r"((r)[3]) : "r"(addr))
#define MMA_BF16(d, a, b0, b1) \
    asm volatile("mma.sync.aligned.m16n8k16.row.col.f32.bf16.bf16.f32 " \
        "{%0,%1,%2,%3}, {%4,%5,%6,%7}, {%8,%9}, {%0,%1,%2,%3};" \
        : "+f"((d)[0]), "+f"((d)[1]), "+f"((d)[2]), "+f"((d)[3]) \
        : "r"((a)[0]), "r"((a)[1]), "r"((a)[2]), "r"((a)[3]), "r"(b0), "r"(b1))

// SW128-style XOR swizzle for 128B rows (16B granules)
#define SWZ(o) ((uint32_t)(o) ^ ((((uint32_t)(o)) >> 3) & 0x70))

// ---------------------------------------------------------------------------
// HMMA GEMM: C[M,1024] = A[M,1024] @ W^T (W stored [N][K] bf16 hi/lo)
//            + bias (+ addv).  2-way bf16 split: hh + hl + lh.
// CTA tile 128x128, warp tile 32x64 (8 warps), K-chunk 64, 2-stage cp.async.
// ---------------------------------------------------------------------------
#define BK 64
#define STAGE_BYTES 65536   // 4 arrays x 128 rows x 128B
#define GEMM_SMEM (2 * STAGE_BYTES)

__global__ __launch_bounds__(256, 1) void gemm_hmma(
    const __nv_bfloat16* __restrict__ Ah, const __nv_bfloat16* __restrict__ Al,
    const __nv_bfloat16* __restrict__ Bh, const __nv_bfloat16* __restrict__ Bl,
    const float* __restrict__ bias, const float* __restrict__ addv,
    float* __restrict__ C)
{
    extern __shared__ char smem[];
    const uint32_t sbase = smem_u32(smem);
    const int tid  = threadIdx.x;
    const int lane = tid & 31;
    const int wid  = tid >> 5;
    const int wm   = wid & 3;        // 0..3 -> m offset wm*32
    const int wn   = wid >> 2;       // 0..1 -> n offset wn*64
    const int brow = blockIdx.y * 128;
    const int bcol = blockIdx.x * 128;

    // ---- load mapping: 2 threads per 128B row, 4x 16B each ----
    const int lrow  = tid >> 1;      // 0..127
    const int lhalf = tid & 1;       // 0 / 1
    const __nv_bfloat16* gAh = Ah + (size_t)(brow + lrow) * DM + lhalf * 32;
    const __nv_bfloat16* gAl = Al + (size_t)(brow + lrow) * DM + lhalf * 32;
    const __nv_bfloat16* gBh = Bh + (size_t)(bcol + lrow) * DM + lhalf * 32;
    const __nv_bfloat16* gBl = Bl + (size_t)(bcol + lrow) * DM + lhalf * 32;
    uint32_t soff[4];
    #pragma unroll
    for (int i = 0; i < 4; ++i)
        soff[i] = SWZ(lrow * 128 + lhalf * 64 + i * 16);

    float acc[2][8][4];
    #pragma unroll
    for (int mi = 0; mi < 2; ++mi)
        #pragma unroll
        for (int nt = 0; nt < 8; ++nt)
            #pragma unroll
            for (int r = 0; r < 4; ++r) acc[mi][nt][r] = 0.f;

    // ldmatrix address components (same scheme for A and B tiles)
    const int frow = lane & 15;                 // row within 16-row tile
    const int fcol = (lane >> 4) << 4;          // 0 or 16 bytes (k half)

    // ---- prologue: load chunk 0 into stage 0 ----
    {
        const uint32_t sb = sbase;
        #pragma unroll
        for (int i = 0; i < 4; ++i) {
            CP_ASYNC16(sb +         soff[i], gAh + i * 8);
            CP_ASYNC16(sb + 16384 + soff[i], gAl + i * 8);
            CP_ASYNC16(sb + 32768 + soff[i], gBh + i * 8);
            CP_ASYNC16(sb + 49152 + soff[i], gBl + i * 8);
        }
        CP_COMMIT();
    }

    #pragma unroll 1
    for (int c = 0; c < 16; ++c) {
        const int s = c & 1;
        if (c + 1 < 16) {
            const uint32_t sb = sbase + ((c + 1) & 1) * STAGE_BYTES;
            const size_t ko = (size_t)(c + 1) * BK;
            #pragma unroll
            for (int i = 0; i < 4; ++i) {
                CP_ASYNC16(sb +         soff[i], gAh + ko + i * 8);
                CP_ASYNC16(sb + 16384 + soff[i], gAl + ko + i * 8);
                CP_ASYNC16(sb + 32768 + soff[i], gBh + ko + i * 8);
                CP_ASYNC16(sb + 49152 + soff[i], gBl + ko + i * 8);
            }
            CP_COMMIT();
            CP_WAIT(1);
        } else {
            CP_WAIT(0);
        }
        __syncthreads();

        const uint32_t stg = sbase + s * STAGE_BYTES;
        #pragma unroll
        for (int ks = 0; ks < 4; ++ks) {
            const uint32_t kb = ks * 32 + fcol;
            uint32_t a_h[2][4], a_l[2][4];
            #pragma unroll
            for (int mi = 0; mi < 2; ++mi) {
                const uint32_t o = SWZ((wm * 32 + mi * 16 + frow) * 128 + kb);
                LDMX4(a_h[mi], stg + o);
                LDMX4(a_l[mi], stg + 16384 + o);
            }
            uint32_t b_h[4][4], b_l[4][4];
            #pragma unroll
            for (int nt2 = 0; nt2 < 4; ++nt2) {
                const uint32_t o = SWZ((wn * 64 + nt2 * 16 + frow) * 128 + kb);
                LDMX4(b_h[nt2], stg + 32768 + o);
                LDMX4(b_l[nt2], stg + 49152 + o);
            }
            // 3 passes (hh, hl, lh) -> same-acc MMAs are 16 apart (no RAW chain)
            #pragma unroll
            for (int mi = 0; mi < 2; ++mi)
                #pragma unroll
                for (int nt = 0; nt < 8; ++nt)
                    MMA_BF16(acc[mi][nt], a_h[mi], b_h[nt >> 1][nt & 1], b_h[nt >> 1][(nt & 1) + 2]);
            #pragma unroll
            for (int mi = 0; mi < 2; ++mi)
                #pragma unroll
                for (int nt = 0; nt < 8; ++nt)
                    MMA_BF16(acc[mi][nt], a_h[mi], b_l[nt >> 1][nt & 1], b_l[nt >> 1][(nt & 1) + 2]);
            #pragma unroll
            for (int mi = 0; mi < 2; ++mi)
                #pragma unroll
                for (int nt = 0; nt < 8; ++nt)
                    MMA_BF16(acc[mi][nt], a_l[mi], b_h[nt >> 1][nt & 1], b_h[nt >> 1][(nt & 1) + 2]);
        }
        __syncthreads();
    }

    // ---- epilogue ----
    const int er = brow + wm * 32 + (lane >> 2);
    const int ec = bcol + wn * 64 + (lane & 3) * 2;
    #pragma unroll
    for (int mi = 0; mi < 2; ++mi) {
        #pragma unroll
        for (int nt = 0; nt < 8; ++nt) {
            const int row = er + mi * 16;
            const int col = ec + nt * 8;
            const float b0 = bias[col], b1 = bias[col + 1];
            float2 o0, o1;
            o0.x = acc[mi][nt][0] + b0; o0.y = acc[mi][nt][1] + b1;
            o1.x = acc[mi][nt][2] + b0; o1.y = acc[mi][nt][3] + b1;
            if (addv) {
                const float2 a0 = *(const float2*)(addv + (size_t)row * DM + col);
                const float2 a1 = *(const float2*)(addv + (size_t)(row + 8) * DM + col);
                o0.x += a0.x; o0.y += a0.y; o1.x += a1.x; o1.y += a1.y;
            }
            *(float2*)(C + (size_t)row * DM + col)       = o0;
            *(float2*)(C + (size_t)(row + 8) * DM + col) = o1;
        }
    }
}

// ---------------------------------------------------------------------------
// fp32 -> bf16 hi/lo split (elementwise, vectorized)
// ---------------------------------------------------------------------------
__global__ __launch_bounds__(256) void split_bf16(
    const float4* __restrict__ x, __nv_bfloat162* __restrict__ hi,
    __nv_bfloat162* __restrict__ lo)
{
    const size_t i = (size_t)blockIdx.x * 256 + threadIdx.x;
    const float4 v = x[i];
    const __nv_bfloat16 hx = __float2bfloat16(v.x);
    const __nv_bfloat16 hy = __float2bfloat16(v.y);
    const __nv_bfloat16 hz = __float2bfloat16(v.z);
    const __nv_bfloat16 hw = __float2bfloat16(v.w);
    hi[2 * i]     = __halves2bfloat162(hx, hy);
    hi[2 * i + 1] = __halves2bfloat162(hz, hw);
    lo[2 * i]     = __halves2bfloat162(__float2bfloat16(v.x - __bfloat162float(hx)),
                                       __float2bfloat16(v.y - __bfloat162float(hy)));
    lo[2 * i + 1] = __halves2bfloat162(__float2bfloat16(v.z - __bfloat162float(hz)),
                                       __float2bfloat16(v.w - __bfloat162float(hw)));
}

// ---------------------------------------------------------------------------
// W [K][N] fp32 -> transposed bf16 hi/lo [N][K]
// ---------------------------------------------------------------------------
__global__ __launch_bounds__(256) void wsplit_t(
    const float* __restrict__ W, __nv_bfloat16* __restrict__ Th,
    __nv_bfloat16* __restrict__ Tl)
{
    __shared__ float tile[32][33];
    const int bn = blockIdx.x * 32;
    const int bk = blockIdx.y * 32;
    const int x = threadIdx.x;   // 0..31
    const int y = threadIdx.y;   // 0..7
    #pragma unroll
    for (int i = 0; i < 32; i += 8)
        tile[y + i][x] = W[(size_t)(bk + y + i) * DM + bn + x];  // [k][n]
    __syncthreads();
    #pragma unroll
    for (int i = 0; i < 32; i += 8) {
        const float v = tile[x][y + i];          // k_local=x, n_local=y+i
        const __nv_bfloat16 h = __float2bfloat16(v);
        Th[(size_t)(bn + y + i) * DM + bk + x] = h;
        Tl[(size_t)(bn + y + i) * DM + bk + x] = __float2bfloat16(v - __bfloat162float(h));
    }
}

// ---------------------------------------------------------------------------
// Small SGEMM: C[M,64] = A[M,1024] @ W[1024,64] + bias, optional scale+mask
// ---------------------------------------------------------------------------
__global__ __launch_bounds__(256) void sgemm_small(
    const float* __restrict__ A, const float* __restrict__ W,
    const float* __restrict__ bias, const float* __restrict__ mask,
    float* __restrict__ C, int Kdim)
{
    __shared__ __align__(16) float As[16][64];
    __shared__ __align__(16) float Bs[16][64];

    const int tid  = threadIdx.x;
    const int brow = blockIdx.y * 64;
    const int arow = tid >> 2;
    const int akof = (tid & 3) * 4;
    const int bkr  = tid >> 4;
    const int bc4  = (tid & 15) * 4;
    const int trow = (tid >> 4) * 4;
    const int tcol = (tid & 15) * 4;

    float acc[4][4];
    #pragma unroll
    for (int i = 0; i < 4; i++)
        #pragma unroll
        for (int j = 0; j < 4; j++) acc[i][j] = 0.f;

    const float* Ab = A + (size_t)(brow + arow) * Kdim + akof;
    const float* Wb = W + (size_t)bkr * HG + bc4;

    for (int k0 = 0; k0 < Kdim; k0 += 16) {
        float4 av = *(const float4*)(Ab + k0);
        As[akof + 0][arow] = av.x;
        As[akof + 1][arow] = av.y;
        As[akof + 2][arow] = av.z;
        As[akof + 3][arow] = av.w;
        float4 bv = *(const float4*)(Wb + (size_t)k0 * HG);
        *(float4*)&Bs[bkr][bc4] = bv;
        __syncthreads();
        #pragma unroll
        for (int kk = 0; kk < 16; kk++) {
            float4 a0 = *(const float4*)&As[kk][trow];
            float4 b0 = *(const float4*)&Bs[kk][tcol];
            float ar[4] = {a0.x, a0.y, a0.z, a0.w};
            float br[4] = {b0.x, b0.y, b0.z, b0.w};
            #pragma unroll
            for (int i = 0; i < 4; i++)
                #pragma unroll
                for (int j = 0; j < 4; j++)
                    acc[i][j] = fmaf(ar[i], br[j], acc[i][j]);
        }
        __syncthreads();
    }

    #pragma unroll
    for (int i = 0; i < 4; i++) {
        const int row = brow + trow + i;
        const float mval = mask ? mask[row] : 0.f;
        #pragma unroll
        for (int j = 0; j < 4; j++) {
            float val = acc[i][j] + bias[tcol + j];
            if (mask) val = val * INV_SCALE + mval;
            C[(size_t)row * HG + tcol + j] = val;
        }
    }
}

// ---------------------------------------------------------------------------
// Softmax over n per (b, col)
// ---------------------------------------------------------------------------
__global__ __launch_bounds__(256) void softmax_n(
    float* __restrict__ s, const float* __restrict__ mask)
{
    const int b   = blockIdx.x / HG;
    const int col = blockIdx.x % HG;
    const int tid = threadIdx.x;
    float* base = s + (size_t)b * SEQ * HG + col;
    const float* mb = mask + (size_t)b * SEQ;

    float vals[16];
    float mx = -1e30f;
    #pragma unroll
    for (int i = 0; i < 16; i++) {
        const int n = tid + i * 256;
        float v = base[(size_t)n * HG] * INV_SCALE + mb[n];
        vals[i] = v;
        mx = fmaxf(mx, v);
    }
    __shared__ float red[256];
    red[tid] = mx; __syncthreads();
    for (int st = 128; st > 0; st >>= 1) {
        if (tid < st) red[tid] = fmaxf(red[tid], red[tid + st]);
        __syncthreads();
    }
    mx = red[0]; __syncthreads();
    float sum = 0.f;
    #pragma unroll
    for (int i = 0; i < 16; i++) { vals[i] = __expf(vals[i] - mx); sum += vals[i]; }
    red[tid] = sum; __syncthreads();
    for (int st = 128; st > 0; st >>= 1) {
        if (tid < st) red[tid] += red[tid + st];
        __syncthreads();
    }
    const float rs = 1.f / red[0];
    #pragma unroll
    for (int i = 0; i < 16; i++) {
        const int n = tid + i * 256;
        base[(size_t)n * HG] = vals[i] * rs;
    }
}

// ---------------------------------------------------------------------------
// g[b,h,d,g] = sum_n w[b,n,h,g] * x[b,n,h*64+d]
// ---------------------------------------------------------------------------
__global__ __launch_bounds__(256) void gsum_k(
    const float* __restrict__ x, const float* __restrict__ w,
    float* __restrict__ out)
{
    const int b = blockIdx.x / NH;
    const int h = blockIdx.x % NH;
    const int g = threadIdx.x >> 6;
    const int d = threadIdx.x & 63;
    const float* xp = x + (size_t)b * SEQ * DM + h * HD + d;
    const float* wp = w + (size_t)b * SEQ * HG + h * NG + g;
    float a0 = 0.f, a1 = 0.f, a2 = 0.f, a3 = 0.f;
    for (int n = 0; n < SEQ; n += 4) {
        a0 = fmaf(xp[(size_t)(n + 0) * DM], wp[(size_t)(n + 0) * HG], a0);
        a1 = fmaf(xp[(size_t)(n + 1) * DM], wp[(size_t)(n + 1) * HG], a1);
        a2 = fmaf(xp[(size_t)(n + 2) * DM], wp[(size_t)(n + 2) * HG], a2);
        a3 = fmaf(xp[(size_t)(n + 3) * DM], wp[(size_t)(n + 3) * HG], a3);
    }
    out[(((size_t)(b * NH + h) * HD) + d) * NG + g] = (a0 + a1) + (a2 + a3);
}

// ---------------------------------------------------------------------------
// out[m, hd] = max_g x[m, hd] * gm[b, h, d, g]
// ---------------------------------------------------------------------------
__global__ __launch_bounds__(256) void maxg_k(
    const float* __restrict__ x, const float* __restrict__ gm,
    float* __restrict__ out)
{
    const size_t i = (size_t)blockIdx.x * 256 + threadIdx.x;
    const int hd = (int)(i & (DM - 1));
    const size_t m = i >> 10;
    const int b = (int)(m >> 12);
    const int h = hd >> 6;
    const int d = hd & 63;
    const float4 gv = *(const float4*)&gm[(((size_t)(b * NH + h) * HD) + d) * NG];
    const float xv = x[i];
    out[i] = fmaxf(fmaxf(xv * gv.x, xv * gv.y), fmaxf(xv * gv.z, xv * gv.w));
}

// ---------------------------------------------------------------------------
// Launch
// ---------------------------------------------------------------------------
extern "C" void kernel_launch(void* const* d_in, const int* in_sizes, int n_in,
                              void* d_out, int out_size)
{
    const float* hs   = (const float*)d_in[0];
    const float* mask = (const float*)d_in[1];
    const float* Wq   = (const float*)d_in[2];
    const float* bq   = (const float*)d_in[3];
    const float* Wqa  = (const float*)d_in[4];
    const float* bqa  = (const float*)d_in[5];
    const float* Wk   = (const float*)d_in[6];
    const float* bk   = (const float*)d_in[7];
    const float* Wka  = (const float*)d_in[8];
    const float* bka  = (const float*)d_in[9];
    const float* Wv   = (const float*)d_in[10];
    const float* bv   = (const float*)d_in[11];
    const float* Wt   = (const float*)d_in[12];
    const float* bt   = (const float*)d_in[13];
    float* out = (float*)d_out;

    float *q, *k, *v, *t, *s1, *s2, *gq, *gk;
    __nv_bfloat16 *ah, *al, *wh, *wl;
    cudaGetSymbolAddress((void**)&q,  g_q);
    cudaGetSymbolAddress((void**)&k,  g_k);
    cudaGetSymbolAddress((void**)&v,  g_v);
    cudaGetSymbolAddress((void**)&t,  g_t);
    cudaGetSymbolAddress((void**)&s1, g_s1);
    cudaGetSymbolAddress((void**)&s2, g_s2);
    cudaGetSymbolAddress((void**)&gq, g_gq);
    cudaGetSymbolAddress((void**)&gk, g_gk);
    cudaGetSymbolAddress((void**)&ah, g_ah);
    cudaGetSymbolAddress((void**)&al, g_al);
    cudaGetSymbolAddress((void**)&wh, g_wh);
    cudaGetSymbolAddress((void**)&wl, g_wl);

    cudaFuncSetAttribute(gemm_hmma, cudaFuncAttributeMaxDynamicSharedMemorySize, GEMM_SMEM);

    const size_t WSZ = (size_t)DM * DM;
    dim3 gW(DM / 32, DM / 32), bW(32, 8);
    dim3 gG(DM / 128, MROWS / 128);          // (8, 256)
    dim3 gSmall(1, MROWS / 64);

    // weight transpose+split (hi/lo bf16, [N][K])
    wsplit_t<<<gW, bW>>>(Wq, wh + 0 * WSZ, wl + 0 * WSZ);
    wsplit_t<<<gW, bW>>>(Wk, wh + 1 * WSZ, wl + 1 * WSZ);
    wsplit_t<<<gW, bW>>>(Wv, wh + 2 * WSZ, wl + 2 * WSZ);
    wsplit_t<<<gW, bW>>>(Wt, wh + 3 * WSZ, wl + 3 * WSZ);

    // split hidden states
    split_bf16<<<(MROWS * DM / 4) / 256, 256>>>((const float4*)hs,
        (__nv_bfloat162*)ah, (__nv_bfloat162*)al);

    // q, k, v projections on HMMA tensor cores
    gemm_hmma<<<gG, 256, GEMM_SMEM>>>(ah, al, wh + 0 * WSZ, wl + 0 * WSZ, bq, nullptr, q);
    gemm_hmma<<<gG, 256, GEMM_SMEM>>>(ah, al, wh + 1 * WSZ, wl + 1 * WSZ, bk, nullptr, k);
    gemm_hmma<<<gG, 256, GEMM_SMEM>>>(ah, al, wh + 2 * WSZ, wl + 2 * WSZ, bv, nullptr, v);

    // q scores -> softmax -> gq -> qk
    sgemm_small<<<gSmall, 256>>>(q, Wqa, bqa, nullptr, s1, DM);
    softmax_n<<<BATCH * HG, 256>>>(s1, mask);
    gsum_k<<<BATCH * NH, 256>>>(q, s1, gq);
    maxg_k<<<(MROWS * DM) / 256, 256>>>(k, gq, t);

    // k scores (no softmax) -> gk -> u
    sgemm_small<<<gSmall, 256>>>(t, Wka, bka, mask, s2, DM);
    gsum_k<<<BATCH * NH, 256>>>(k, s2, gk);
    maxg_k<<<(MROWS * DM) / 256, 256>>>(v, gk, t);

    // out = u @ Wt + bt + q  (split u, then HMMA)
    split_bf16<<<(MROWS * DM / 4) / 256, 256>>>((const float4*)t,
        (__nv_bfloat162*)ah, (__nv_bfloat162*)al);
    gemm_hmma<<<gG, 256, GEMM_SMEM>>>(ah, al, wh + 3 * WSZ, wl + 3 * WSZ, bt, q, out);
}

// round 4
// speedup vs baseline: 2.3236x; 1.2865x over previous
#include <cuda_runtime.h>
#include <cuda_fp16.h>
#include <cstdint>

// Problem constants
#define BATCH 8
#define SEQ   4096
#define DM    1024
#define NH    16
#define NG    4
#define HD    64
#define HG    (NH*NG)          // 64
#define MROWS (BATCH*SEQ)      // 32768
#define INV_SCALE 0.125f       // 1/sqrt(64)
#define WSCALE 1024.0f         // weights pre-scaled by 2^10 (fp16 subnormal guard)
#define WUNSCALE (1.0f/1024.0f)

// ---------------------------------------------------------------------------
// Scratch (device globals: allocation-free per harness rules)
// ---------------------------------------------------------------------------
__device__ float g_q [MROWS * DM];
__device__ float g_k [MROWS * DM];
__device__ float g_v [MROWS * DM];
__device__ float g_t [MROWS * DM];
__device__ float g_s1[MROWS * HG];
__device__ float g_s2[MROWS * HG];
__device__ float g_gq[BATCH * NH * HD * NG];
__device__ float g_gk[BATCH * NH * HD * NG];
// fp16 A operand (hs, then u — reused)
__device__ __align__(256) __half g_ah[MROWS * DM];
// transposed + scaled + split weights [N][K] fp16
__device__ __align__(256) __half g_wh[4][DM * DM];
__device__ __align__(256) __half g_wl[4][DM * DM];

// ---------------------------------------------------------------------------
// PTX helpers (plain sm_103-safe: mma.sync / ldmatrix / cp.async only)
// ---------------------------------------------------------------------------
__device__ __forceinline__ uint32_t smem_u32(const void* p) {
    uint32_t a;
    asm("{ .reg .u64 t; cvta.to.shared.u64 t, %1; cvt.u32.u64 %0, t; }"
        : "=r"(a) : "l"(p));
    return a;
}
#define CP_ASYNC16(s, g) \
    asm volatile("cp.async.cg.shared.global [%0], [%1], 16;" :: "r"(s), "l"(g))
#define CP_COMMIT() asm volatile("cp.async.commit_group;" ::: "memory")
#define CP_WAIT(n)  asm volatile("cp.async.wait_group %0;" :: "n"(n) : "memory")
#define LDMX4(r, addr) \
    asm volatile("ldmatrix.sync.aligned.m8n8.x4.shared.b16 {%0,%1,%2,%3}, [%4];" \
        : "=r"((r)[0]), "=r"((r)[1]), "=r"((r)[2]), "=r"((r)[3]) : "r"(addr))
#define MMA_F16(d, a, b0, b1) \
    asm volatile("mma.sync.aligned.m16n8k16.row.col.f32.f16.f16.f32 " \
        "{%0,%1,%2,%3}, {%4,%5,%6,%7}, {%8,%9}, {%0,%1,%2,%3};" \
        : "+f"((d)[0]), "+f"((d)[1]), "+f"((d)[2]), "+f"((d)[3]) \
        : "r"((a)[0]), "r"((a)[1]), "r"((a)[2]), "r"((a)[3]), "r"(b0), "r"(b1))

// SW128-style XOR swizzle for 128B rows (16B granules)
#define SWZ(o) ((uint32_t)(o) ^ ((((uint32_t)(o)) >> 3) & 0x70))

// ---------------------------------------------------------------------------
// HMMA GEMM: C[M,1024] = A[M,1024] @ W^T + bias (+ addv)
// A single fp16; W stored [N][K] fp16 (scaled x1024), split hi/lo -> 2 MMAs.
// CTA tile 128x128, warp tile 32x64 (8 warps), K-chunk 64, 2-stage cp.async.
// ---------------------------------------------------------------------------
#define BK 64
#define STAGE_BYTES 49152   // A(16K) + Bh(16K) + Bl(16K)
#define GEMM_SMEM (2 * STAGE_BYTES)

__global__ __launch_bounds__(256, 1) void gemm_hmma(
    const __half* __restrict__ A,
    const __half* __restrict__ Bh, const __half* __restrict__ Bl,
    const float* __restrict__ bias, const float* __restrict__ addv,
    float* __restrict__ C)
{
    extern __shared__ char smem[];
    const uint32_t sbase = smem_u32(smem);
    const int tid  = threadIdx.x;
    const int lane = tid & 31;
    const int wid  = tid >> 5;
    const int wm   = wid & 3;        // m offset wm*32
    const int wn   = wid >> 2;       // n offset wn*64
    const int brow = blockIdx.y * 128;
    const int bcol = blockIdx.x * 128;

    // load mapping: 2 threads per 128B row, 4x 16B each
    const int lrow  = tid >> 1;      // 0..127
    const int lhalf = tid & 1;
    const __half* gA  = A  + (size_t)(brow + lrow) * DM + lhalf * 32;
    const __half* gBh = Bh + (size_t)(bcol + lrow) * DM + lhalf * 32;
    const __half* gBl = Bl + (size_t)(bcol + lrow) * DM + lhalf * 32;
    uint32_t soff[4];
    #pragma unroll
    for (int i = 0; i < 4; ++i)
        soff[i] = SWZ(lrow * 128 + lhalf * 64 + i * 16);

    float acc[2][8][4];
    #pragma unroll
    for (int mi = 0; mi < 2; ++mi)
        #pragma unroll
        for (int nt = 0; nt < 8; ++nt)
            #pragma unroll
            for (int r = 0; r < 4; ++r) acc[mi][nt][r] = 0.f;

    const int frow = lane & 15;
    const int fcol = (lane >> 4) << 4;

    // prologue: chunk 0 -> stage 0
    {
        const uint32_t sb = sbase;
        #pragma unroll
        for (int i = 0; i < 4; ++i) {
            CP_ASYNC16(sb +         soff[i], gA  + i * 8);
            CP_ASYNC16(sb + 16384 + soff[i], gBh + i * 8);
            CP_ASYNC16(sb + 32768 + soff[i], gBl + i * 8);
        }
        CP_COMMIT();
    }

    #pragma unroll 1
    for (int c = 0; c < 16; ++c) {
        const int s = c & 1;
        if (c + 1 < 16) {
            const uint32_t sb = sbase + ((c + 1) & 1) * STAGE_BYTES;
            const size_t ko = (size_t)(c + 1) * BK;
            #pragma unroll
            for (int i = 0; i < 4; ++i) {
                CP_ASYNC16(sb +         soff[i], gA  + ko + i * 8);
                CP_ASYNC16(sb + 16384 + soff[i], gBh + ko + i * 8);
                CP_ASYNC16(sb + 32768 + soff[i], gBl + ko + i * 8);
            }
            CP_COMMIT();
            CP_WAIT(1);
        } else {
            CP_WAIT(0);
        }
        __syncthreads();

        const uint32_t stg = sbase + s * STAGE_BYTES;
        #pragma unroll
        for (int ks = 0; ks < 4; ++ks) {
            const uint32_t kb = ks * 32 + fcol;
            uint32_t a_r[2][4];
            #pragma unroll
            for (int mi = 0; mi < 2; ++mi) {
                const uint32_t o = SWZ((wm * 32 + mi * 16 + frow) * 128 + kb);
                LDMX4(a_r[mi], stg + o);
            }
            uint32_t b_h[4][4], b_l[4][4];
            #pragma unroll
            for (int nt2 = 0; nt2 < 4; ++nt2) {
                const uint32_t o = SWZ((wn * 64 + nt2 * 16 + frow) * 128 + kb);
                LDMX4(b_h[nt2], stg + 16384 + o);
                LDMX4(b_l[nt2], stg + 32768 + o);
            }
            // 2 passes (a*bh, a*bl) -> same-acc MMAs 16 apart (no RAW chain)
            #pragma unroll
            for (int mi = 0; mi < 2; ++mi)
                #pragma unroll
                for (int nt = 0; nt < 8; ++nt)
                    MMA_F16(acc[mi][nt], a_r[mi], b_h[nt >> 1][nt & 1], b_h[nt >> 1][(nt & 1) + 2]);
            #pragma unroll
            for (int mi = 0; mi < 2; ++mi)
                #pragma unroll
                for (int nt = 0; nt < 8; ++nt)
                    MMA_F16(acc[mi][nt], a_r[mi], b_l[nt >> 1][nt & 1], b_l[nt >> 1][(nt & 1) + 2]);
        }
        __syncthreads();
    }

    // epilogue: unscale (weights were x1024), add bias (+addv)
    const int er = brow + wm * 32 + (lane >> 2);
    const int ec = bcol + wn * 64 + (lane & 3) * 2;
    #pragma unroll
    for (int mi = 0; mi < 2; ++mi) {
        #pragma unroll
        for (int nt = 0; nt < 8; ++nt) {
            const int row = er + mi * 16;
            const int col = ec + nt * 8;
            const float b0 = bias[col], b1 = bias[col + 1];
            float2 o0, o1;
            o0.x = acc[mi][nt][0] * WUNSCALE + b0; o0.y = acc[mi][nt][1] * WUNSCALE + b1;
            o1.x = acc[mi][nt][2] * WUNSCALE + b0; o1.y = acc[mi][nt][3] * WUNSCALE + b1;
            if (addv) {
                const float2 a0 = *(const float2*)(addv + (size_t)row * DM + col);
                const float2 a1 = *(const float2*)(addv + (size_t)(row + 8) * DM + col);
                o0.x += a0.x; o0.y += a0.y; o1.x += a1.x; o1.y += a1.y;
            }
            *(float2*)(C + (size_t)row * DM + col)       = o0;
            *(float2*)(C + (size_t)(row + 8) * DM + col) = o1;
        }
    }
}

// ---------------------------------------------------------------------------
// fp32 -> fp16 convert (elementwise, vectorized)
// ---------------------------------------------------------------------------
__global__ __launch_bounds__(256) void tofp16(
    const float4* __restrict__ x, __half2* __restrict__ o)
{
    const size_t i = (size_t)blockIdx.x * 256 + threadIdx.x;
    const float4 v = x[i];
    o[2 * i]     = __floats2half2_rn(v.x, v.y);
    o[2 * i + 1] = __floats2half2_rn(v.z, v.w);
}

// ---------------------------------------------------------------------------
// W [K][N] fp32 -> transposed, x1024-scaled fp16 hi/lo [N][K]
// ---------------------------------------------------------------------------
__global__ __launch_bounds__(256) void wsplit_t(
    const float* __restrict__ W, __half* __restrict__ Th,
    __half* __restrict__ Tl)
{
    __shared__ float tile[32][33];
    const int bn = blockIdx.x * 32;
    const int bk = blockIdx.y * 32;
    const int x = threadIdx.x;   // 0..31
    const int y = threadIdx.y;   // 0..7
    #pragma unroll
    for (int i = 0; i < 32; i += 8)
        tile[y + i][x] = W[(size_t)(bk + y + i) * DM + bn + x];  // [k][n]
    __syncthreads();
    #pragma unroll
    for (int i = 0; i < 32; i += 8) {
        const float v = tile[x][y + i] * WSCALE;     // k_local=x, n_local=y+i
        const __half h = __float2half_rn(v);
        Th[(size_t)(bn + y + i) * DM + bk + x] = h;
        Tl[(size_t)(bn + y + i) * DM + bk + x] = __float2half_rn(v - __half2float(h));
    }
}

// ---------------------------------------------------------------------------
// Small SGEMM: C[M,64] = A[M,1024] @ W[1024,64] + bias, optional scale+mask
// ---------------------------------------------------------------------------
__global__ __launch_bounds__(256) void sgemm_small(
    const float* __restrict__ A, const float* __restrict__ W,
    const float* __restrict__ bias, const float* __restrict__ mask,
    float* __restrict__ C, int Kdim)
{
    __shared__ __align__(16) float As[16][64];
    __shared__ __align__(16) float Bs[16][64];

    const int tid  = threadIdx.x;
    const int brow = blockIdx.y * 64;
    const int arow = tid >> 2;
    const int akof = (tid & 3) * 4;
    const int bkr  = tid >> 4;
    const int bc4  = (tid & 15) * 4;
    const int trow = (tid >> 4) * 4;
    const int tcol = (tid & 15) * 4;

    float acc[4][4];
    #pragma unroll
    for (int i = 0; i < 4; i++)
        #pragma unroll
        for (int j = 0; j < 4; j++) acc[i][j] = 0.f;

    const float* Ab = A + (size_t)(brow + arow) * Kdim + akof;
    const float* Wb = W + (size_t)bkr * HG + bc4;

    for (int k0 = 0; k0 < Kdim; k0 += 16) {
        float4 av = *(const float4*)(Ab + k0);
        As[akof + 0][arow] = av.x;
        As[akof + 1][arow] = av.y;
        As[akof + 2][arow] = av.z;
        As[akof + 3][arow] = av.w;
        float4 bv = *(const float4*)(Wb + (size_t)k0 * HG);
        *(float4*)&Bs[bkr][bc4] = bv;
        __syncthreads();
        #pragma unroll
        for (int kk = 0; kk < 16; kk++) {
            float4 a0 = *(const float4*)&As[kk][trow];
            float4 b0 = *(const float4*)&Bs[kk][tcol];
            float ar[4] = {a0.x, a0.y, a0.z, a0.w};
            float br[4] = {b0.x, b0.y, b0.z, b0.w};
            #pragma unroll
            for (int i = 0; i < 4; i++)
                #pragma unroll
                for (int j = 0; j < 4; j++)
                    acc[i][j] = fmaf(ar[i], br[j], acc[i][j]);
        }
        __syncthreads();
    }

    #pragma unroll
    for (int i = 0; i < 4; i++) {
        const int row = brow + trow + i;
        const float mval = mask ? mask[row] : 0.f;
        #pragma unroll
        for (int j = 0; j < 4; j++) {
            float val = acc[i][j] + bias[tcol + j];
            if (mask) val = val * INV_SCALE + mval;
            C[(size_t)row * HG + tcol + j] = val;
        }
    }
}

// ---------------------------------------------------------------------------
// Softmax over n per (b, col)
// ---------------------------------------------------------------------------
__global__ __launch_bounds__(256) void softmax_n(
    float* __restrict__ s, const float* __restrict__ mask)
{
    const int b   = blockIdx.x / HG;
    const int col = blockIdx.x % HG;
    const int tid = threadIdx.x;
    float* base = s + (size_t)b * SEQ * HG + col;
    const float* mb = mask + (size_t)b * SEQ;

    float vals[16];
    float mx = -1e30f;
    #pragma unroll
    for (int i = 0; i < 16; i++) {
        const int n = tid + i * 256;
        float v = base[(size_t)n * HG] * INV_SCALE + mb[n];
        vals[i] = v;
        mx = fmaxf(mx, v);
    }
    __shared__ float red[256];
    red[tid] = mx; __syncthreads();
    for (int st = 128; st > 0; st >>= 1) {
        if (tid < st) red[tid] = fmaxf(red[tid], red[tid + st]);
        __syncthreads();
    }
    mx = red[0]; __syncthreads();
    float sum = 0.f;
    #pragma unroll
    for (int i = 0; i < 16; i++) { vals[i] = __expf(vals[i] - mx); sum += vals[i]; }
    red[tid] = sum; __syncthreads();
    for (int st = 128; st > 0; st >>= 1) {
        if (tid < st) red[tid] += red[tid + st];
        __syncthreads();
    }
    const float rs = 1.f / red[0];
    #pragma unroll
    for (int i = 0; i < 16; i++) {
        const int n = tid + i * 256;
        base[(size_t)n * HG] = vals[i] * rs;
    }
}

// ---------------------------------------------------------------------------
// g[b,h,d,g] = sum_n w[b,n,h,g] * x[b,n,h*64+d]
// ---------------------------------------------------------------------------
__global__ __launch_bounds__(256) void gsum_k(
    const float* __restrict__ x, const float* __restrict__ w,
    float* __restrict__ out)
{
    const int b = blockIdx.x / NH;
    const int h = blockIdx.x % NH;
    const int g = threadIdx.x >> 6;
    const int d = threadIdx.x & 63;
    const float* xp = x + (size_t)b * SEQ * DM + h * HD + d;
    const float* wp = w + (size_t)b * SEQ * HG + h * NG + g;
    float a0 = 0.f, a1 = 0.f, a2 = 0.f, a3 = 0.f;
    for (int n = 0; n < SEQ; n += 4) {
        a0 = fmaf(xp[(size_t)(n + 0) * DM], wp[(size_t)(n + 0) * HG], a0);
        a1 = fmaf(xp[(size_t)(n + 1) * DM], wp[(size_t)(n + 1) * HG], a1);
        a2 = fmaf(xp[(size_t)(n + 2) * DM], wp[(size_t)(n + 2) * HG], a2);
        a3 = fmaf(xp[(size_t)(n + 3) * DM], wp[(size_t)(n + 3) * HG], a3);
    }
    out[(((size_t)(b * NH + h) * HD) + d) * NG + g] = (a0 + a1) + (a2 + a3);
}

// ---------------------------------------------------------------------------
// out[m, hd] = max_g x[m, hd] * gm[b, h, d, g]    (fp32 output)
// ---------------------------------------------------------------------------
__global__ __launch_bounds__(256) void maxg_k(
    const float* __restrict__ x, const float* __restrict__ gm,
    float* __restrict__ out)
{
    const size_t i = (size_t)blockIdx.x * 256 + threadIdx.x;
    const int hd = (int)(i & (DM - 1));
    const size_t m = i >> 10;
    const int b = (int)(m >> 12);
    const int h = hd >> 6;
    const int d = hd & 63;
    const float4 gv = *(const float4*)&gm[(((size_t)(b * NH + h) * HD) + d) * NG];
    const float xv = x[i];
    out[i] = fmaxf(fmaxf(xv * gv.x, xv * gv.y), fmaxf(xv * gv.z, xv * gv.w));
}

// ---------------------------------------------------------------------------
// same, but writes fp16 directly (feeds final GEMM A operand)
// ---------------------------------------------------------------------------
__global__ __launch_bounds__(256) void maxg_h(
    const float* __restrict__ x, const float* __restrict__ gm,
    __half* __restrict__ out)
{
    const size_t i = (size_t)blockIdx.x * 256 + threadIdx.x;
    const int hd = (int)(i & (DM - 1));
    const size_t m = i >> 10;
    const int b = (int)(m >> 12);
    const int h = hd >> 6;
    const int d = hd & 63;
    const float4 gv = *(const float4*)&gm[(((size_t)(b * NH + h) * HD) + d) * NG];
    const float xv = x[i];
    out[i] = __float2half_rn(
        fmaxf(fmaxf(xv * gv.x, xv * gv.y), fmaxf(xv * gv.z, xv * gv.w)));
}

// ---------------------------------------------------------------------------
// Launch
// ---------------------------------------------------------------------------
extern "C" void kernel_launch(void* const* d_in, const int* in_sizes, int n_in,
                              void* d_out, int out_size)
{
    const float* hs   = (const float*)d_in[0];
    const float* mask = (const float*)d_in[1];
    const float* Wq   = (const float*)d_in[2];
    const float* bq   = (const float*)d_in[3];
    const float* Wqa  = (const float*)d_in[4];
    const float* bqa  = (const float*)d_in[5];
    const float* Wk   = (const float*)d_in[6];
    const float* bk   = (const float*)d_in[7];
    const float* Wka  = (const float*)d_in[8];
    const float* bka  = (const float*)d_in[9];
    const float* Wv   = (const float*)d_in[10];
    const float* bv   = (const float*)d_in[11];
    const float* Wt   = (const float*)d_in[12];
    const float* bt   = (const float*)d_in[13];
    float* out = (float*)d_out;

    float *q, *k, *v, *t, *s1, *s2, *gq, *gk;
    __half *ah, *wh, *wl;
    cudaGetSymbolAddress((void**)&q,  g_q);
    cudaGetSymbolAddress((void**)&k,  g_k);
    cudaGetSymbolAddress((void**)&v,  g_v);
    cudaGetSymbolAddress((void**)&t,  g_t);
    cudaGetSymbolAddress((void**)&s1, g_s1);
    cudaGetSymbolAddress((void**)&s2, g_s2);
    cudaGetSymbolAddress((void**)&gq, g_gq);
    cudaGetSymbolAddress((void**)&gk, g_gk);
    cudaGetSymbolAddress((void**)&ah, g_ah);
    cudaGetSymbolAddress((void**)&wh, g_wh);
    cudaGetSymbolAddress((void**)&wl, g_wl);

    cudaFuncSetAttribute(gemm_hmma, cudaFuncAttributeMaxDynamicSharedMemorySize, GEMM_SMEM);

    const size_t WSZ = (size_t)DM * DM;
    dim3 gW(DM / 32, DM / 32), bW(32, 8);
    dim3 gG(DM / 128, MROWS / 128);          // (8, 256)
    dim3 gSmall(1, MROWS / 64);

    // weight transpose + x1024 scale + fp16 hi/lo split, [N][K]
    wsplit_t<<<gW, bW>>>(Wq, wh + 0 * WSZ, wl + 0 * WSZ);
    wsplit_t<<<gW, bW>>>(Wk, wh + 1 * WSZ, wl + 1 * WSZ);
    wsplit_t<<<gW, bW>>>(Wv, wh + 2 * WSZ, wl + 2 * WSZ);
    wsplit_t<<<gW, bW>>>(Wt, wh + 3 * WSZ, wl + 3 * WSZ);

    // hidden states -> fp16
    tofp16<<<(MROWS * DM / 4) / 256, 256>>>((const float4*)hs, (__half2*)ah);

    // q, k, v projections (HMMA, 2-MMA weight split)
    gemm_hmma<<<gG, 256, GEMM_SMEM>>>(ah, wh + 0 * WSZ, wl + 0 * WSZ, bq, nullptr, q);
    gemm_hmma<<<gG, 256, GEMM_SMEM>>>(ah, wh + 1 * WSZ, wl + 1 * WSZ, bk, nullptr, k);
    gemm_hmma<<<gG, 256, GEMM_SMEM>>>(ah, wh + 2 * WSZ, wl + 2 * WSZ, bv, nullptr, v);

    // q scores -> softmax -> gq -> qk
    sgemm_small<<<gSmall, 256>>>(q, Wqa, bqa, nullptr, s1, DM);
    softmax_n<<<BATCH * HG, 256>>>(s1, mask);
    gsum_k<<<BATCH * NH, 256>>>(q, s1, gq);
    maxg_k<<<(MROWS * DM) / 256, 256>>>(k, gq, t);

    // k scores (no softmax) -> gk -> u (fp16, feeds final GEMM directly)
    sgemm_small<<<gSmall, 256>>>(t, Wka, bka, mask, s2, DM);
    gsum_k<<<BATCH * NH, 256>>>(k, s2, gk);
    maxg_h<<<(MROWS * DM) / 256, 256>>>(v, gk, ah);

    // out = u @ Wt + bt + q
    gemm_hmma<<<gG, 256, GEMM_SMEM>>>(ah, wh + 3 * WSZ, wl + 3 * WSZ, bt, q, out);
}

// round 5
// speedup vs baseline: 4.2596x; 1.8332x over previous
#include <cuda_runtime.h>
#include <cuda_fp16.h>
#include <cstdint>

// Problem constants
#define BATCH 8
#define SEQ   4096
#define DM    1024
#define NH    16
#define NG    4
#define HD    64
#define HG    (NH*NG)          // 64
#define MROWS (BATCH*SEQ)      // 32768
#define INV_SCALE 0.125f       // 1/sqrt(64)
#define WSCALE 1024.0f         // weights pre-scaled by 2^10 (fp16 precision guard)
#define WUNSCALE (1.0f/1024.0f)

// ---------------------------------------------------------------------------
// Scratch (device globals: zero-initialized, allocation-free)
// ---------------------------------------------------------------------------
__device__ float g_q [MROWS * DM];
__device__ float g_k [MROWS * DM];
__device__ float g_v [MROWS * DM];
__device__ float g_s1[MROWS * HG];
__device__ float g_s2[MROWS * HG];       // also reused as WqWqa fp32 tmp (64K floats)
__device__ float g_gq[BATCH * NH * HD * NG];
__device__ float g_gk[BATCH * NH * HD * NG];
__device__ float g_b1[HG];               // combined bias: bq@Wqa + bqa
__device__ float g_zero[HG];             // zeros
// fp16 A operand (hs, then qk, then u — sequentially reused)
__device__ __align__(256) __half g_ah[MROWS * DM];
// transposed fp16 weights [N][K], x1024
__device__ __align__(256) __half g_wh[4][DM * DM];
__device__ __align__(256) __half g_ws1[HG * DM];   // (Wq@Wqa)^T
__device__ __align__(256) __half g_ws2[HG * DM];   // Wka^T

// ---------------------------------------------------------------------------
// PTX helpers (plain sm_103-safe)
// ---------------------------------------------------------------------------
__device__ __forceinline__ uint32_t smem_u32(const void* p) {
    uint32_t a;
    asm("{ .reg .u64 t; cvta.to.shared.u64 t, %1; cvt.u32.u64 %0, t; }"
        : "=r"(a) : "l"(p));
    return a;
}
#define CP_ASYNC16(s, g) \
    asm volatile("cp.async.cg.shared.global [%0], [%1], 16;" :: "r"(s), "l"(g))
#define CP_COMMIT() asm volatile("cp.async.commit_group;" ::: "memory")
#define CP_WAIT(n)  asm volatile("cp.async.wait_group %0;" :: "n"(n) : "memory")
#define LDMX4(r, addr) \
    asm volatile("ldmatrix.sync.aligned.m8n8.x4.shared.b16 {%0,%1,%2,%3}, [%4];" \
        : "=r"((r)[0]), "=r"((r)[1]), "=r"((r)[2]), "=r"((r)[3]) : "r"(addr))
#define MMA_F16(d, a, b0, b1) \
    asm volatile("mma.sync.aligned.m16n8k16.row.col.f32.f16.f16.f32 " \
        "{%0,%1,%2,%3}, {%4,%5,%6,%7}, {%8,%9}, {%0,%1,%2,%3};" \
        : "+f"((d)[0]), "+f"((d)[1]), "+f"((d)[2]), "+f"((d)[3]) \
        : "r"((a)[0]), "r"((a)[1]), "r"((a)[2]), "r"((a)[3]), "r"(b0), "r"(b1))

#define SWZ(o) ((uint32_t)(o) ^ ((((uint32_t)(o)) >> 3) & 0x70))

// ---------------------------------------------------------------------------
// Big HMMA GEMM: C[M,1024] = A[M,1024] @ W^T + bias (+ addv).  Single fp16 MMA.
// CTA 128x128, warp 32x64 (8 warps), K-chunk 64, 2-stage cp.async.
// ---------------------------------------------------------------------------
#define BK 64
#define STG_BIG 32768                 // A(16K) + B(16K)
#define SMEM_BIG (2 * STG_BIG)

__global__ __launch_bounds__(256, 1) void gemm_hmma(
    const __half* __restrict__ A, const __half* __restrict__ B,
    const float* __restrict__ bias, const float* __restrict__ addv,
    float* __restrict__ C)
{
    extern __shared__ char smem[];
    const uint32_t sbase = smem_u32(smem);
    const int tid  = threadIdx.x;
    const int lane = tid & 31;
    const int wid  = tid >> 5;
    const int wm   = wid & 3;
    const int wn   = wid >> 2;
    const int brow = blockIdx.y * 128;
    const int bcol = blockIdx.x * 128;

    const int lrow  = tid >> 1;
    const int lhalf = tid & 1;
    const __half* gA = A + (size_t)(brow + lrow) * DM + lhalf * 32;
    const __half* gB = B + (size_t)(bcol + lrow) * DM + lhalf * 32;
    uint32_t soff[4];
    #pragma unroll
    for (int i = 0; i < 4; ++i)
        soff[i] = SWZ(lrow * 128 + lhalf * 64 + i * 16);

    float acc[2][8][4];
    #pragma unroll
    for (int mi = 0; mi < 2; ++mi)
        #pragma unroll
        for (int nt = 0; nt < 8; ++nt)
            #pragma unroll
            for (int r = 0; r < 4; ++r) acc[mi][nt][r] = 0.f;

    const int frow = lane & 15;
    const int fcol = (lane >> 4) << 4;

    {
        #pragma unroll
        for (int i = 0; i < 4; ++i) {
            CP_ASYNC16(sbase +         soff[i], gA + i * 8);
            CP_ASYNC16(sbase + 16384 + soff[i], gB + i * 8);
        }
        CP_COMMIT();
    }

    #pragma unroll 1
    for (int c = 0; c < 16; ++c) {
        const int s = c & 1;
        if (c + 1 < 16) {
            const uint32_t sb = sbase + ((c + 1) & 1) * STG_BIG;
            const size_t ko = (size_t)(c + 1) * BK;
            #pragma unroll
            for (int i = 0; i < 4; ++i) {
                CP_ASYNC16(sb +         soff[i], gA + ko + i * 8);
                CP_ASYNC16(sb + 16384 + soff[i], gB + ko + i * 8);
            }
            CP_COMMIT();
            CP_WAIT(1);
        } else {
            CP_WAIT(0);
        }
        __syncthreads();

        const uint32_t stg = sbase + s * STG_BIG;
        #pragma unroll
        for (int ks = 0; ks < 4; ++ks) {
            const uint32_t kb = ks * 32 + fcol;
            uint32_t a_r[2][4];
            #pragma unroll
            for (int mi = 0; mi < 2; ++mi) {
                const uint32_t o = SWZ((wm * 32 + mi * 16 + frow) * 128 + kb);
                LDMX4(a_r[mi], stg + o);
            }
            uint32_t b_r[4][4];
            #pragma unroll
            for (int nt2 = 0; nt2 < 4; ++nt2) {
                const uint32_t o = SWZ((wn * 64 + nt2 * 16 + frow) * 128 + kb);
                LDMX4(b_r[nt2], stg + 16384 + o);
            }
            #pragma unroll
            for (int mi = 0; mi < 2; ++mi)
                #pragma unroll
                for (int nt = 0; nt < 8; ++nt)
                    MMA_F16(acc[mi][nt], a_r[mi], b_r[nt >> 1][nt & 1], b_r[nt >> 1][(nt & 1) + 2]);
        }
        __syncthreads();
    }

    const int er = brow + wm * 32 + (lane >> 2);
    const int ec = bcol + wn * 64 + (lane & 3) * 2;
    #pragma unroll
    for (int mi = 0; mi < 2; ++mi) {
        #pragma unroll
        for (int nt = 0; nt < 8; ++nt) {
            const int row = er + mi * 16;
            const int col = ec + nt * 8;
            const float b0 = bias[col], b1 = bias[col + 1];
            float2 o0, o1;
            o0.x = acc[mi][nt][0] * WUNSCALE + b0; o0.y = acc[mi][nt][1] * WUNSCALE + b1;
            o1.x = acc[mi][nt][2] * WUNSCALE + b0; o1.y = acc[mi][nt][3] * WUNSCALE + b1;
            if (addv) {
                const float2 a0 = *(const float2*)(addv + (size_t)row * DM + col);
                const float2 a1 = *(const float2*)(addv + (size_t)(row + 8) * DM + col);
                o0.x += a0.x; o0.y += a0.y; o1.x += a1.x; o1.y += a1.y;
            }
            *(float2*)(C + (size_t)row * DM + col)       = o0;
            *(float2*)(C + (size_t)(row + 8) * DM + col) = o1;
        }
    }
}

// ---------------------------------------------------------------------------
// N=64 HMMA GEMM: C[M,64] = A[M,1024] @ W^T + bias, optional (val/8 + mask).
// CTA 128x64, warp 32x32 (8 warps), K-chunk 64, 2-stage cp.async.
// ---------------------------------------------------------------------------
#define STG_N64 24576                 // A(16K) + B(8K)
#define SMEM_N64 (2 * STG_N64)

__global__ __launch_bounds__(256, 1) void gemm_n64(
    const __half* __restrict__ A, const __half* __restrict__ B,
    const float* __restrict__ bias, const float* __restrict__ mask,
    float* __restrict__ C)
{
    extern __shared__ char smem[];
    const uint32_t sbase = smem_u32(smem);
    const int tid  = threadIdx.x;
    const int lane = tid & 31;
    const int wid  = tid >> 5;
    const int wm   = wid & 3;        // rows wm*32
    const int wn   = wid >> 2;       // cols wn*32
    const int brow = blockIdx.x * 128;

    const int lrow  = tid >> 1;
    const int lhalf = tid & 1;
    const __half* gA = A + (size_t)(brow + lrow) * DM + lhalf * 32;
    uint32_t aoff[4];
    #pragma unroll
    for (int i = 0; i < 4; ++i)
        aoff[i] = SWZ(lrow * 128 + lhalf * 64 + i * 16);
    // B loaders: threads 0..127, 2 per row (64 rows)
    const int  brw   = (tid & 127) >> 1;
    const int  bhalf = tid & 1;
    const bool bldr  = tid < 128;
    const __half* gB = B + (size_t)brw * DM + bhalf * 32;
    uint32_t boff[4];
    #pragma unroll
    for (int i = 0; i < 4; ++i)
        boff[i] = SWZ(brw * 128 + bhalf * 64 + i * 16);

    float acc[2][4][4];
    #pragma unroll
    for (int mi = 0; mi < 2; ++mi)
        #pragma unroll
        for (int nt = 0; nt < 4; ++nt)
            #pragma unroll
            for (int r = 0; r < 4; ++r) acc[mi][nt][r] = 0.f;

    const int frow = lane & 15;
    const int fcol = (lane >> 4) << 4;

    {
        #pragma unroll
        for (int i = 0; i < 4; ++i) {
            CP_ASYNC16(sbase + aoff[i], gA + i * 8);
            if (bldr) CP_ASYNC16(sbase + 16384 + boff[i], gB + i * 8);
        }
        CP_COMMIT();
    }

    #pragma unroll 1
    for (int c = 0; c < 16; ++c) {
        const int s = c & 1;
        if (c + 1 < 16) {
            const uint32_t sb = sbase + ((c + 1) & 1) * STG_N64;
            const size_t ko = (size_t)(c + 1) * BK;
            #pragma unroll
            for (int i = 0; i < 4; ++i) {
                CP_ASYNC16(sb + aoff[i], gA + ko + i * 8);
                if (bldr) CP_ASYNC16(sb + 16384 + boff[i], gB + ko + i * 8);
            }
            CP_COMMIT();
            CP_WAIT(1);
        } else {
            CP_WAIT(0);
        }
        __syncthreads();

        const uint32_t stg = sbase + s * STG_N64;
        #pragma unroll
        for (int ks = 0; ks < 4; ++ks) {
            const uint32_t kb = ks * 32 + fcol;
            uint32_t a_r[2][4];
            #pragma unroll
            for (int mi = 0; mi < 2; ++mi) {
                const uint32_t o = SWZ((wm * 32 + mi * 16 + frow) * 128 + kb);
                LDMX4(a_r[mi], stg + o);
            }
            uint32_t b_r[2][4];
            #pragma unroll
            for (int nt2 = 0; nt2 < 2; ++nt2) {
                const uint32_t o = SWZ((wn * 32 + nt2 * 16 + frow) * 128 + kb);
                LDMX4(b_r[nt2], stg + 16384 + o);
            }
            #pragma unroll
            for (int mi = 0; mi < 2; ++mi)
                #pragma unroll
                for (int nt = 0; nt < 4; ++nt)
                    MMA_F16(acc[mi][nt], a_r[mi], b_r[nt >> 1][nt & 1], b_r[nt >> 1][(nt & 1) + 2]);
        }
        __syncthreads();
    }

    const int er = brow + wm * 32 + (lane >> 2);
    const int ec = wn * 32 + (lane & 3) * 2;
    #pragma unroll
    for (int mi = 0; mi < 2; ++mi) {
        #pragma unroll
        for (int nt = 0; nt < 4; ++nt) {
            const int row = er + mi * 16;
            const int col = ec + nt * 8;
            const float b0 = bias[col], b1 = bias[col + 1];
            float v00 = acc[mi][nt][0] * WUNSCALE + b0;
            float v01 = acc[mi][nt][1] * WUNSCALE + b1;
            float v10 = acc[mi][nt][2] * WUNSCALE + b0;
            float v11 = acc[mi][nt][3] * WUNSCALE + b1;
            if (mask) {
                const float m0 = mask[row], m1 = mask[row + 8];
                v00 = v00 * INV_SCALE + m0; v01 = v01 * INV_SCALE + m0;
                v10 = v10 * INV_SCALE + m1; v11 = v11 * INV_SCALE + m1;
            }
            *(float2*)(C + (size_t)row * HG + col)       = make_float2(v00, v01);
            *(float2*)(C + (size_t)(row + 8) * HG + col) = make_float2(v10, v11);
        }
    }
}

// ---------------------------------------------------------------------------
// fp32 -> fp16 convert
// ---------------------------------------------------------------------------
__global__ __launch_bounds__(256) void tofp16(
    const float4* __restrict__ x, __half2* __restrict__ o)
{
    const size_t i = (size_t)blockIdx.x * 256 + threadIdx.x;
    const float4 v = x[i];
    o[2 * i]     = __floats2half2_rn(v.x, v.y);
    o[2 * i + 1] = __floats2half2_rn(v.z, v.w);
}

// ---------------------------------------------------------------------------
// W [K=1024][ncols] fp32 -> transposed x1024 fp16 [ncols][1024]
// ---------------------------------------------------------------------------
__global__ __launch_bounds__(256) void wconv_t(
    const float* __restrict__ W, __half* __restrict__ T, int ncols)
{
    __shared__ float tile[32][33];
    const int bn = blockIdx.x * 32;
    const int bk = blockIdx.y * 32;
    const int x = threadIdx.x;
    const int y = threadIdx.y;
    #pragma unroll
    for (int i = 0; i < 32; i += 8)
        tile[y + i][x] = W[(size_t)(bk + y + i) * ncols + bn + x];
    __syncthreads();
    #pragma unroll
    for (int i = 0; i < 32; i += 8)
        T[(size_t)(bn + y + i) * DM + bk + x] =
            __float2half_rn(tile[x][y + i] * WSCALE);
}

// ---------------------------------------------------------------------------
// fp32 small GEMM (weight-prep only): C[M,64] = A[M,1024] @ W[1024,64] + bias
// ---------------------------------------------------------------------------
__global__ __launch_bounds__(256) void sgemm_small(
    const float* __restrict__ A, const float* __restrict__ W,
    const float* __restrict__ bias, float* __restrict__ C)
{
    __shared__ __align__(16) float As[16][64];
    __shared__ __align__(16) float Bs[16][64];
    const int tid  = threadIdx.x;
    const int brow = blockIdx.y * 64;
    const int arow = tid >> 2;
    const int akof = (tid & 3) * 4;
    const int bkr  = tid >> 4;
    const int bc4  = (tid & 15) * 4;
    const int trow = (tid >> 4) * 4;
    const int tcol = (tid & 15) * 4;

    float acc[4][4];
    #pragma unroll
    for (int i = 0; i < 4; i++)
        #pragma unroll
        for (int j = 0; j < 4; j++) acc[i][j] = 0.f;

    const float* Ab = A + (size_t)(brow + arow) * DM + akof;
    const float* Wb = W + (size_t)bkr * HG + bc4;

    for (int k0 = 0; k0 < DM; k0 += 16) {
        float4 av = *(const float4*)(Ab + k0);
        As[akof + 0][arow] = av.x;
        As[akof + 1][arow] = av.y;
        As[akof + 2][arow] = av.z;
        As[akof + 3][arow] = av.w;
        float4 bv = *(const float4*)(Wb + (size_t)k0 * HG);
        *(float4*)&Bs[bkr][bc4] = bv;
        __syncthreads();
        #pragma unroll
        for (int kk = 0; kk < 16; kk++) {
            float4 a0 = *(const float4*)&As[kk][trow];
            float4 b0 = *(const float4*)&Bs[kk][tcol];
            float ar[4] = {a0.x, a0.y, a0.z, a0.w};
            float br[4] = {b0.x, b0.y, b0.z, b0.w};
            #pragma unroll
            for (int i = 0; i < 4; i++)
                #pragma unroll
                for (int j = 0; j < 4; j++)
                    acc[i][j] = fmaf(ar[i], br[j], acc[i][j]);
        }
        __syncthreads();
    }
    #pragma unroll
    for (int i = 0; i < 4; i++)
        #pragma unroll
        for (int j = 0; j < 4; j++)
            C[(size_t)(brow + trow + i) * HG + tcol + j] = acc[i][j] + bias[tcol + j];
}

// ---------------------------------------------------------------------------
// combined bias: b1[j] = bqa[j] + sum_i bq[i] * Wqa[i][j]   (one block, 256 thr)
// ---------------------------------------------------------------------------
__global__ void bias_comb(const float* __restrict__ bq,
                          const float* __restrict__ Wqa,
                          const float* __restrict__ bqa,
                          float* __restrict__ b1)
{
    __shared__ float part[4][HG];
    const int j = threadIdx.x & 63;
    const int p = threadIdx.x >> 6;          // 4 chunks of 256
    float s = 0.f;
    for (int i = p * 256; i < (p + 1) * 256; ++i)
        s = fmaf(bq[i], Wqa[(size_t)i * HG + j], s);
    part[p][j] = s;
    __syncthreads();
    if (p == 0)
        b1[j] = bqa[j] + ((part[0][j] + part[1][j]) + (part[2][j] + part[3][j]));
}

// ---------------------------------------------------------------------------
// zero gq/gk
// ---------------------------------------------------------------------------
__global__ __launch_bounds__(256) void zero2(float* __restrict__ a,
                                             float* __restrict__ b)
{
    const int i = blockIdx.x * 256 + threadIdx.x;
    a[i] = 0.f; b[i] = 0.f;
}

// ---------------------------------------------------------------------------
// Softmax over n per (b, col)
// ---------------------------------------------------------------------------
__global__ __launch_bounds__(256) void softmax_n(
    float* __restrict__ s, const float* __restrict__ mask)
{
    const int b   = blockIdx.x / HG;
    const int col = blockIdx.x % HG;
    const int tid = threadIdx.x;
    float* base = s + (size_t)b * SEQ * HG + col;
    const float* mb = mask + (size_t)b * SEQ;

    float vals[16];
    float mx = -1e30f;
    #pragma unroll
    for (int i = 0; i < 16; i++) {
        const int n = tid + i * 256;
        float v = base[(size_t)n * HG] * INV_SCALE + mb[n];
        vals[i] = v;
        mx = fmaxf(mx, v);
    }
    __shared__ float red[256];
    red[tid] = mx; __syncthreads();
    for (int st = 128; st > 0; st >>= 1) {
        if (tid < st) red[tid] = fmaxf(red[tid], red[tid + st]);
        __syncthreads();
    }
    mx = red[0]; __syncthreads();
    float sum = 0.f;
    #pragma unroll
    for (int i = 0; i < 16; i++) { vals[i] = __expf(vals[i] - mx); sum += vals[i]; }
    red[tid] = sum; __syncthreads();
    for (int st = 128; st > 0; st >>= 1) {
        if (tid < st) red[tid] += red[tid + st];
        __syncthreads();
    }
    const float rs = 1.f / red[0];
    #pragma unroll
    for (int i = 0; i < 16; i++) {
        const int n = tid + i * 256;
        base[(size_t)n * HG] = vals[i] * rs;
    }
}

// ---------------------------------------------------------------------------
// gsum (split-n + atomic): g[b,h,d,g] += sum_{n in chunk} w[b,n,h,g] x[b,n,h*64+d]
// grid (BATCH*NH, 16); 256 n per chunk
// ---------------------------------------------------------------------------
__global__ __launch_bounds__(256) void gsum_k(
    const float* __restrict__ x, const float* __restrict__ w,
    float* __restrict__ out)
{
    const int b = blockIdx.x / NH;
    const int h = blockIdx.x % NH;
    const int n0 = blockIdx.y * 256;
    const int g = threadIdx.x >> 6;
    const int d = threadIdx.x & 63;
    const float* xp = x + ((size_t)b * SEQ + n0) * DM + h * HD + d;
    const float* wp = w + ((size_t)b * SEQ + n0) * HG + h * NG + g;
    float a0 = 0.f, a1 = 0.f, a2 = 0.f, a3 = 0.f;
    #pragma unroll 4
    for (int n = 0; n < 256; n += 4) {
        a0 = fmaf(xp[(size_t)(n + 0) * DM], wp[(size_t)(n + 0) * HG], a0);
        a1 = fmaf(xp[(size_t)(n + 1) * DM], wp[(size_t)(n + 1) * HG], a1);
        a2 = fmaf(xp[(size_t)(n + 2) * DM], wp[(size_t)(n + 2) * HG], a2);
        a3 = fmaf(xp[(size_t)(n + 3) * DM], wp[(size_t)(n + 3) * HG], a3);
    }
    atomicAdd(&out[(((size_t)(b * NH + h) * HD) + d) * NG + g],
              (a0 + a1) + (a2 + a3));
}

// ---------------------------------------------------------------------------
// out[m, hd] = max_g x[m, hd] * gm[b,h,d,g]   (fp16 output)
// ---------------------------------------------------------------------------
__global__ __launch_bounds__(256) void maxg_h(
    const float* __restrict__ x, const float* __restrict__ gm,
    __half* __restrict__ out)
{
    const size_t i = (size_t)blockIdx.x * 256 + threadIdx.x;
    const int hd = (int)(i & (DM - 1));
    const size_t m = i >> 10;
    const int b = (int)(m >> 12);
    const int h = hd >> 6;
    const int d = hd & 63;
    const float4 gv = *(const float4*)&gm[(((size_t)(b * NH + h) * HD) + d) * NG];
    const float xv = x[i];
    out[i] = __float2half_rn(
        fmaxf(fmaxf(xv * gv.x, xv * gv.y), fmaxf(xv * gv.z, xv * gv.w)));
}

// ---------------------------------------------------------------------------
// Launch
// ---------------------------------------------------------------------------
extern "C" void kernel_launch(void* const* d_in, const int* in_sizes, int n_in,
                              void* d_out, int out_size)
{
    const float* hs   = (const float*)d_in[0];
    const float* mask = (const float*)d_in[1];
    const float* Wq   = (const float*)d_in[2];
    const float* bq   = (const float*)d_in[3];
    const float* Wqa  = (const float*)d_in[4];
    const float* bqa  = (const float*)d_in[5];
    const float* Wk   = (const float*)d_in[6];
    const float* bk   = (const float*)d_in[7];
    const float* Wka  = (const float*)d_in[8];
    const float* bka  = (const float*)d_in[9];
    const float* Wv   = (const float*)d_in[10];
    const float* bv   = (const float*)d_in[11];
    const float* Wt   = (const float*)d_in[12];
    const float* bt   = (const float*)d_in[13];
    float* out = (float*)d_out;

    float *q, *k, *v, *s1, *s2, *gq, *gk, *b1, *zv;
    __half *ah, *wh, *ws1, *ws2;
    cudaGetSymbolAddress((void**)&q,   g_q);
    cudaGetSymbolAddress((void**)&k,   g_k);
    cudaGetSymbolAddress((void**)&v,   g_v);
    cudaGetSymbolAddress((void**)&s1,  g_s1);
    cudaGetSymbolAddress((void**)&s2,  g_s2);
    cudaGetSymbolAddress((void**)&gq,  g_gq);
    cudaGetSymbolAddress((void**)&gk,  g_gk);
    cudaGetSymbolAddress((void**)&b1,  g_b1);
    cudaGetSymbolAddress((void**)&zv,  g_zero);
    cudaGetSymbolAddress((void**)&ah,  g_ah);
    cudaGetSymbolAddress((void**)&wh,  g_wh);
    cudaGetSymbolAddress((void**)&ws1, g_ws1);
    cudaGetSymbolAddress((void**)&ws2, g_ws2);

    cudaFuncSetAttribute(gemm_hmma, cudaFuncAttributeMaxDynamicSharedMemorySize, SMEM_BIG);
    cudaFuncSetAttribute(gemm_n64,  cudaFuncAttributeMaxDynamicSharedMemorySize, SMEM_N64);

    const size_t WSZ = (size_t)DM * DM;
    dim3 gW(DM / 32, DM / 32), bW(32, 8);
    dim3 gW64(HG / 32, DM / 32);
    dim3 gG(DM / 128, MROWS / 128);          // (8, 256)
    dim3 gGs(BATCH * NH, SEQ / 256);         // (128, 16)

    // --- prep ---
    zero2<<<(BATCH * NH * HD * NG) / 256, 256>>>(gq, gk);
    wconv_t<<<gW, bW>>>(Wq, wh + 0 * WSZ, DM);
    wconv_t<<<gW, bW>>>(Wk, wh + 1 * WSZ, DM);
    wconv_t<<<gW, bW>>>(Wv, wh + 2 * WSZ, DM);
    wconv_t<<<gW, bW>>>(Wt, wh + 3 * WSZ, DM);
    // WqWqa (fp32, into s2 tmp) -> transposed fp16; combined bias
    sgemm_small<<<dim3(1, DM / 64), 256>>>(Wq, Wqa, zv, s2);
    wconv_t<<<gW64, bW>>>(s2, ws1, HG);
    bias_comb<<<1, 256>>>(bq, Wqa, bqa, b1);
    wconv_t<<<gW64, bW>>>(Wka, ws2, HG);
    // hidden states -> fp16
    tofp16<<<(MROWS * DM / 4) / 256, 256>>>((const float4*)hs, (__half2*)ah);

    // --- q, k, v projections (single-MMA HMMA) ---
    gemm_hmma<<<gG, 256, SMEM_BIG>>>(ah, wh + 0 * WSZ, bq, nullptr, q);
    gemm_hmma<<<gG, 256, SMEM_BIG>>>(ah, wh + 1 * WSZ, bk, nullptr, k);
    gemm_hmma<<<gG, 256, SMEM_BIG>>>(ah, wh + 2 * WSZ, bv, nullptr, v);

    // --- q scores (fused hs@(Wq@Wqa)+b1) -> softmax -> gq -> qk(fp16) ---
    gemm_n64<<<MROWS / 128, 256, SMEM_N64>>>(ah, ws1, b1, nullptr, s1);
    softmax_n<<<BATCH * HG, 256>>>(s1, mask);
    gsum_k<<<gGs, 256>>>(q, s1, gq);
    maxg_h<<<(MROWS * DM) / 256, 256>>>(k, gq, ah);

    // --- k scores -> gk -> u(fp16) ---
    gemm_n64<<<MROWS / 128, 256, SMEM_N64>>>(ah, ws2, bka, mask, s2);
    gsum_k<<<gGs, 256>>>(k, s2, gk);
    maxg_h<<<(MROWS * DM) / 256, 256>>>(v, gk, ah);

    // --- out = u @ Wt + bt + q ---
    gemm_hmma<<<gG, 256, SMEM_BIG>>>(ah, wh + 3 * WSZ, bt, q, out);
}

// round 6
// speedup vs baseline: 4.7987x; 1.1266x over previous
#include <cuda_runtime.h>
#include <cuda_fp16.h>
#include <cstdint>

// Problem constants
#define BATCH 8
#define SEQ   4096
#define DM    1024
#define NH    16
#define NG    4
#define HD    64
#define HG    (NH*NG)          // 64
#define MROWS (BATCH*SEQ)      // 32768
#define INV_SCALE 0.125f       // 1/sqrt(64)
#define WSCALE 1024.0f         // weights pre-scaled by 2^10 (fp16 precision guard)
#define WUNSCALE (1.0f/1024.0f)

// ---------------------------------------------------------------------------
// Scratch (device globals)
// ---------------------------------------------------------------------------
__device__ float g_q [MROWS * DM];              // q fp32 (residual + gsum)
__device__ float g_s1[MROWS * HG];
__device__ float g_s2[MROWS * HG];              // also WqWqa fp32 tmp during prep
__device__ float g_gq[BATCH * NH * HD * NG];
__device__ float g_gk[BATCH * NH * HD * NG];
__device__ float g_b1[HG];                      // combined bias bq@Wqa + bqa
__device__ float g_zero[HG];
__device__ __align__(256) __half g_kh[MROWS * DM];   // k fp16
__device__ __align__(256) __half g_vh[MROWS * DM];   // v fp16
__device__ __align__(256) __half g_ah[MROWS * DM];   // hs -> qk -> u (reused)
__device__ __align__(256) __half g_wh[4][DM * DM];   // Wq,Wk,Wv,Wt transposed x1024
__device__ __align__(256) __half g_ws1[HG * DM];     // (Wq@Wqa)^T
__device__ __align__(256) __half g_ws2[HG * DM];     // Wka^T

// ---------------------------------------------------------------------------
// PTX helpers (plain sm_103-safe)
// ---------------------------------------------------------------------------
__device__ __forceinline__ uint32_t smem_u32(const void* p) {
    uint32_t a;
    asm("{ .reg .u64 t; cvta.to.shared.u64 t, %1; cvt.u32.u64 %0, t; }"
        : "=r"(a) : "l"(p));
    return a;
}
#define CP_ASYNC16(s, g) \
    asm volatile("cp.async.cg.shared.global [%0], [%1], 16;" :: "r"(s), "l"(g))
#define CP_COMMIT() asm volatile("cp.async.commit_group;" ::: "memory")
#define CP_WAIT(n)  asm volatile("cp.async.wait_group %0;" :: "n"(n) : "memory")
#define LDMX4(r, addr) \
    asm volatile("ldmatrix.sync.aligned.m8n8.x4.shared.b16 {%0,%1,%2,%3}, [%4];" \
        : "=r"((r)[0]), "=r"((r)[1]), "=r"((r)[2]), "=r"((r)[3]) : "r"(addr))
#define MMA_F16(d, a, b0, b1) \
    asm volatile("mma.sync.aligned.m16n8k16.row.col.f32.f16.f16.f32 " \
        "{%0,%1,%2,%3}, {%4,%5,%6,%7}, {%8,%9}, {%0,%1,%2,%3};" \
        : "+f"((d)[0]), "+f"((d)[1]), "+f"((d)[2]), "+f"((d)[3]) \
        : "r"((a)[0]), "r"((a)[1]), "r"((a)[2]), "r"((a)[3]), "r"(b0), "r"(b1))

#define SWZ(o) ((uint32_t)(o) ^ ((((uint32_t)(o)) >> 3) & 0x70))

#define BK 64
#define STG_BIG 32768                 // A(16K) + B(16K)
#define SMEM_BIG (2 * STG_BIG)

// ---------------------------------------------------------------------------
// Fused QKV GEMM: for all 3 weights (concat [3072][1024] fp16).
// which = bcol>>10: 0 -> q fp32, 1 -> k fp16, 2 -> v fp16.
// CTA 128x128, 8 warps (32x64), 2-stage cp.async, occupancy 2.
// ---------------------------------------------------------------------------
__global__ __launch_bounds__(256, 2) void gemm_qkv(
    const __half* __restrict__ A, const __half* __restrict__ B3,
    const float* __restrict__ bq, const float* __restrict__ bk,
    const float* __restrict__ bv,
    float* __restrict__ Q, __half* __restrict__ K, __half* __restrict__ V)
{
    extern __shared__ char smem[];
    const uint32_t sbase = smem_u32(smem);
    const int tid  = threadIdx.x;
    const int lane = tid & 31;
    const int wid  = tid >> 5;
    const int wm   = wid & 3;
    const int wn   = wid >> 2;
    const int brow = blockIdx.y * 128;
    const int bcol = blockIdx.x * 128;
    const int which = bcol >> 10;
    const int bcl   = bcol & (DM - 1);
    const float* bias = which == 0 ? bq : (which == 1 ? bk : bv);

    const int lrow  = tid >> 1;
    const int lhalf = tid & 1;
    const __half* gA = A  + (size_t)(brow + lrow) * DM + lhalf * 32;
    const __half* gB = B3 + (size_t)(bcol + lrow) * DM + lhalf * 32;
    uint32_t soff[4];
    #pragma unroll
    for (int i = 0; i < 4; ++i)
        soff[i] = SWZ(lrow * 128 + lhalf * 64 + i * 16);

    float acc[2][8][4];
    #pragma unroll
    for (int mi = 0; mi < 2; ++mi)
        #pragma unroll
        for (int nt = 0; nt < 8; ++nt)
            #pragma unroll
            for (int r = 0; r < 4; ++r) acc[mi][nt][r] = 0.f;

    const int frow = lane & 15;
    const int fcol = (lane >> 4) << 4;

    {
        #pragma unroll
        for (int i = 0; i < 4; ++i) {
            CP_ASYNC16(sbase +         soff[i], gA + i * 8);
            CP_ASYNC16(sbase + 16384 + soff[i], gB + i * 8);
        }
        CP_COMMIT();
    }

    #pragma unroll 1
    for (int c = 0; c < 16; ++c) {
        const int s = c & 1;
        if (c + 1 < 16) {
            const uint32_t sb = sbase + ((c + 1) & 1) * STG_BIG;
            const size_t ko = (size_t)(c + 1) * BK;
            #pragma unroll
            for (int i = 0; i < 4; ++i) {
                CP_ASYNC16(sb +         soff[i], gA + ko + i * 8);
                CP_ASYNC16(sb + 16384 + soff[i], gB + ko + i * 8);
            }
            CP_COMMIT();
            CP_WAIT(1);
        } else {
            CP_WAIT(0);
        }
        __syncthreads();

        const uint32_t stg = sbase + s * STG_BIG;
        #pragma unroll
        for (int ks = 0; ks < 4; ++ks) {
            const uint32_t kb = ks * 32 + fcol;
            uint32_t a_r[2][4];
            #pragma unroll
            for (int mi = 0; mi < 2; ++mi) {
                const uint32_t o = SWZ((wm * 32 + mi * 16 + frow) * 128 + kb);
                LDMX4(a_r[mi], stg + o);
            }
            uint32_t b_r[4][4];
            #pragma unroll
            for (int nt2 = 0; nt2 < 4; ++nt2) {
                const uint32_t o = SWZ((wn * 64 + nt2 * 16 + frow) * 128 + kb);
                LDMX4(b_r[nt2], stg + 16384 + o);
            }
            #pragma unroll
            for (int mi = 0; mi < 2; ++mi)
                #pragma unroll
                for (int nt = 0; nt < 8; ++nt)
                    MMA_F16(acc[mi][nt], a_r[mi], b_r[nt >> 1][nt & 1], b_r[nt >> 1][(nt & 1) + 2]);
        }
        __syncthreads();
    }

    const int er = brow + wm * 32 + (lane >> 2);
    const int ec = bcl + wn * 64 + (lane & 3) * 2;
    __half* Ch = which == 1 ? K : V;
    #pragma unroll
    for (int mi = 0; mi < 2; ++mi) {
        #pragma unroll
        for (int nt = 0; nt < 8; ++nt) {
            const int row = er + mi * 16;
            const int col = ec + nt * 8;
            const float b0 = bias[col], b1 = bias[col + 1];
            const float v00 = acc[mi][nt][0] * WUNSCALE + b0;
            const float v01 = acc[mi][nt][1] * WUNSCALE + b1;
            const float v10 = acc[mi][nt][2] * WUNSCALE + b0;
            const float v11 = acc[mi][nt][3] * WUNSCALE + b1;
            if (which == 0) {
                *(float2*)(Q + (size_t)row * DM + col)       = make_float2(v00, v01);
                *(float2*)(Q + (size_t)(row + 8) * DM + col) = make_float2(v10, v11);
            } else {
                *(__half2*)(Ch + (size_t)row * DM + col)       = __floats2half2_rn(v00, v01);
                *(__half2*)(Ch + (size_t)(row + 8) * DM + col) = __floats2half2_rn(v10, v11);
            }
        }
    }
}

// ---------------------------------------------------------------------------
// Big HMMA GEMM (final): C[M,1024] = A@W^T + bias + addv
// ---------------------------------------------------------------------------
__global__ __launch_bounds__(256, 2) void gemm_hmma(
    const __half* __restrict__ A, const __half* __restrict__ B,
    const float* __restrict__ bias, const float* __restrict__ addv,
    float* __restrict__ C)
{
    extern __shared__ char smem[];
    const uint32_t sbase = smem_u32(smem);
    const int tid  = threadIdx.x;
    const int lane = tid & 31;
    const int wid  = tid >> 5;
    const int wm   = wid & 3;
    const int wn   = wid >> 2;
    const int brow = blockIdx.y * 128;
    const int bcol = blockIdx.x * 128;

    const int lrow  = tid >> 1;
    const int lhalf = tid & 1;
    const __half* gA = A + (size_t)(brow + lrow) * DM + lhalf * 32;
    const __half* gB = B + (size_t)(bcol + lrow) * DM + lhalf * 32;
    uint32_t soff[4];
    #pragma unroll
    for (int i = 0; i < 4; ++i)
        soff[i] = SWZ(lrow * 128 + lhalf * 64 + i * 16);

    float acc[2][8][4];
    #pragma unroll
    for (int mi = 0; mi < 2; ++mi)
        #pragma unroll
        for (int nt = 0; nt < 8; ++nt)
            #pragma unroll
            for (int r = 0; r < 4; ++r) acc[mi][nt][r] = 0.f;

    const int frow = lane & 15;
    const int fcol = (lane >> 4) << 4;

    {
        #pragma unroll
        for (int i = 0; i < 4; ++i) {
            CP_ASYNC16(sbase +         soff[i], gA + i * 8);
            CP_ASYNC16(sbase + 16384 + soff[i], gB + i * 8);
        }
        CP_COMMIT();
    }

    #pragma unroll 1
    for (int c = 0; c < 16; ++c) {
        const int s = c & 1;
        if (c + 1 < 16) {
            const uint32_t sb = sbase + ((c + 1) & 1) * STG_BIG;
            const size_t ko = (size_t)(c + 1) * BK;
            #pragma unroll
            for (int i = 0; i < 4; ++i) {
                CP_ASYNC16(sb +         soff[i], gA + ko + i * 8);
                CP_ASYNC16(sb + 16384 + soff[i], gB + ko + i * 8);
            }
            CP_COMMIT();
            CP_WAIT(1);
        } else {
            CP_WAIT(0);
        }
        __syncthreads();

        const uint32_t stg = sbase + s * STG_BIG;
        #pragma unroll
        for (int ks = 0; ks < 4; ++ks) {
            const uint32_t kb = ks * 32 + fcol;
            uint32_t a_r[2][4];
            #pragma unroll
            for (int mi = 0; mi < 2; ++mi) {
                const uint32_t o = SWZ((wm * 32 + mi * 16 + frow) * 128 + kb);
                LDMX4(a_r[mi], stg + o);
            }
            uint32_t b_r[4][4];
            #pragma unroll
            for (int nt2 = 0; nt2 < 4; ++nt2) {
                const uint32_t o = SWZ((wn * 64 + nt2 * 16 + frow) * 128 + kb);
                LDMX4(b_r[nt2], stg + 16384 + o);
            }
            #pragma unroll
            for (int mi = 0; mi < 2; ++mi)
                #pragma unroll
                for (int nt = 0; nt < 8; ++nt)
                    MMA_F16(acc[mi][nt], a_r[mi], b_r[nt >> 1][nt & 1], b_r[nt >> 1][(nt & 1) + 2]);
        }
        __syncthreads();
    }

    const int er = brow + wm * 32 + (lane >> 2);
    const int ec = bcol + wn * 64 + (lane & 3) * 2;
    #pragma unroll
    for (int mi = 0; mi < 2; ++mi) {
        #pragma unroll
        for (int nt = 0; nt < 8; ++nt) {
            const int row = er + mi * 16;
            const int col = ec + nt * 8;
            const float b0 = bias[col], b1 = bias[col + 1];
            float2 o0, o1;
            o0.x = acc[mi][nt][0] * WUNSCALE + b0; o0.y = acc[mi][nt][1] * WUNSCALE + b1;
            o1.x = acc[mi][nt][2] * WUNSCALE + b0; o1.y = acc[mi][nt][3] * WUNSCALE + b1;
            const float2 a0 = *(const float2*)(addv + (size_t)row * DM + col);
            const float2 a1 = *(const float2*)(addv + (size_t)(row + 8) * DM + col);
            o0.x += a0.x; o0.y += a0.y; o1.x += a1.x; o1.y += a1.y;
            *(float2*)(C + (size_t)row * DM + col)       = o0;
            *(float2*)(C + (size_t)(row + 8) * DM + col) = o1;
        }
    }
}

// ---------------------------------------------------------------------------
// N=64 HMMA GEMM: C[M,64] = A[M,1024] @ W^T + bias, optional (val/8 + mask)
// ---------------------------------------------------------------------------
#define STG_N64 24576
#define SMEM_N64 (2 * STG_N64)

__global__ __launch_bounds__(256, 2) void gemm_n64(
    const __half* __restrict__ A, const __half* __restrict__ B,
    const float* __restrict__ bias, const float* __restrict__ mask,
    float* __restrict__ C)
{
    extern __shared__ char smem[];
    const uint32_t sbase = smem_u32(smem);
    const int tid  = threadIdx.x;
    const int lane = tid & 31;
    const int wid  = tid >> 5;
    const int wm   = wid & 3;
    const int wn   = wid >> 2;
    const int brow = blockIdx.x * 128;

    const int lrow  = tid >> 1;
    const int lhalf = tid & 1;
    const __half* gA = A + (size_t)(brow + lrow) * DM + lhalf * 32;
    uint32_t aoff[4];
    #pragma unroll
    for (int i = 0; i < 4; ++i)
        aoff[i] = SWZ(lrow * 128 + lhalf * 64 + i * 16);
    const int  brw   = (tid & 127) >> 1;
    const int  bhalf = tid & 1;
    const bool bldr  = tid < 128;
    const __half* gB = B + (size_t)brw * DM + bhalf * 32;
    uint32_t boff[4];
    #pragma unroll
    for (int i = 0; i < 4; ++i)
        boff[i] = SWZ(brw * 128 + bhalf * 64 + i * 16);

    float acc[2][4][4];
    #pragma unroll
    for (int mi = 0; mi < 2; ++mi)
        #pragma unroll
        for (int nt = 0; nt < 4; ++nt)
            #pragma unroll
            for (int r = 0; r < 4; ++r) acc[mi][nt][r] = 0.f;

    const int frow = lane & 15;
    const int fcol = (lane >> 4) << 4;

    {
        #pragma unroll
        for (int i = 0; i < 4; ++i) {
            CP_ASYNC16(sbase + aoff[i], gA + i * 8);
            if (bldr) CP_ASYNC16(sbase + 16384 + boff[i], gB + i * 8);
        }
        CP_COMMIT();
    }

    #pragma unroll 1
    for (int c = 0; c < 16; ++c) {
        const int s = c & 1;
        if (c + 1 < 16) {
            const uint32_t sb = sbase + ((c + 1) & 1) * STG_N64;
            const size_t ko = (size_t)(c + 1) * BK;
            #pragma unroll
            for (int i = 0; i < 4; ++i) {
                CP_ASYNC16(sb + aoff[i], gA + ko + i * 8);
                if (bldr) CP_ASYNC16(sb + 16384 + boff[i], gB + ko + i * 8);
            }
            CP_COMMIT();
            CP_WAIT(1);
        } else {
            CP_WAIT(0);
        }
        __syncthreads();

        const uint32_t stg = sbase + s * STG_N64;
        #pragma unroll
        for (int ks = 0; ks < 4; ++ks) {
            const uint32_t kb = ks * 32 + fcol;
            uint32_t a_r[2][4];
            #pragma unroll
            for (int mi = 0; mi < 2; ++mi) {
                const uint32_t o = SWZ((wm * 32 + mi * 16 + frow) * 128 + kb);
                LDMX4(a_r[mi], stg + o);
            }
            uint32_t b_r[2][4];
            #pragma unroll
            for (int nt2 = 0; nt2 < 2; ++nt2) {
                const uint32_t o = SWZ((wn * 32 + nt2 * 16 + frow) * 128 + kb);
                LDMX4(b_r[nt2], stg + 16384 + o);
            }
            #pragma unroll
            for (int mi = 0; mi < 2; ++mi)
                #pragma unroll
                for (int nt = 0; nt < 4; ++nt)
                    MMA_F16(acc[mi][nt], a_r[mi], b_r[nt >> 1][nt & 1], b_r[nt >> 1][(nt & 1) + 2]);
        }
        __syncthreads();
    }

    const int er = brow + wm * 32 + (lane >> 2);
    const int ec = wn * 32 + (lane & 3) * 2;
    #pragma unroll
    for (int mi = 0; mi < 2; ++mi) {
        #pragma unroll
        for (int nt = 0; nt < 4; ++nt) {
            const int row = er + mi * 16;
            const int col = ec + nt * 8;
            const float b0 = bias[col], b1 = bias[col + 1];
            float v00 = acc[mi][nt][0] * WUNSCALE + b0;
            float v01 = acc[mi][nt][1] * WUNSCALE + b1;
            float v10 = acc[mi][nt][2] * WUNSCALE + b0;
            float v11 = acc[mi][nt][3] * WUNSCALE + b1;
            if (mask) {
                const float m0 = mask[row], m1 = mask[row + 8];
                v00 = v00 * INV_SCALE + m0; v01 = v01 * INV_SCALE + m0;
                v10 = v10 * INV_SCALE + m1; v11 = v11 * INV_SCALE + m1;
            }
            *(float2*)(C + (size_t)row * HG + col)       = make_float2(v00, v01);
            *(float2*)(C + (size_t)(row + 8) * HG + col) = make_float2(v10, v11);
        }
    }
}

// ---------------------------------------------------------------------------
// fp32 -> fp16 convert
// ---------------------------------------------------------------------------
__global__ __launch_bounds__(256) void tofp16(
    const float4* __restrict__ x, __half2* __restrict__ o)
{
    const size_t i = (size_t)blockIdx.x * 256 + threadIdx.x;
    const float4 v = x[i];
    o[2 * i]     = __floats2half2_rn(v.x, v.y);
    o[2 * i + 1] = __floats2half2_rn(v.z, v.w);
}

// ---------------------------------------------------------------------------
// 4x batched W [1024][1024] fp32 -> transposed x1024 fp16 (z selects matrix)
// ---------------------------------------------------------------------------
__global__ __launch_bounds__(256) void wconv4(
    const float* __restrict__ W0, const float* __restrict__ W1,
    const float* __restrict__ W2, const float* __restrict__ W3,
    __half* __restrict__ T)
{
    __shared__ float tile[32][33];
    const int z = blockIdx.z;
    const float* W = z == 0 ? W0 : z == 1 ? W1 : z == 2 ? W2 : W3;
    __half* Tz = T + (size_t)z * DM * DM;
    const int bn = blockIdx.x * 32;
    const int bk = blockIdx.y * 32;
    const int x = threadIdx.x;
    const int y = threadIdx.y;
    #pragma unroll
    for (int i = 0; i < 32; i += 8)
        tile[y + i][x] = W[(size_t)(bk + y + i) * DM + bn + x];
    __syncthreads();
    #pragma unroll
    for (int i = 0; i < 32; i += 8)
        Tz[(size_t)(bn + y + i) * DM + bk + x] =
            __float2half_rn(tile[x][y + i] * WSCALE);
}

// ---------------------------------------------------------------------------
// W [K=1024][ncols] fp32 -> transposed x1024 fp16 [ncols][1024]
// ---------------------------------------------------------------------------
__global__ __launch_bounds__(256) void wconv_t(
    const float* __restrict__ W, __half* __restrict__ T, int ncols)
{
    __shared__ float tile[32][33];
    const int bn = blockIdx.x * 32;
    const int bk = blockIdx.y * 32;
    const int x = threadIdx.x;
    const int y = threadIdx.y;
    #pragma unroll
    for (int i = 0; i < 32; i += 8)
        tile[y + i][x] = W[(size_t)(bk + y + i) * ncols + bn + x];
    __syncthreads();
    #pragma unroll
    for (int i = 0; i < 32; i += 8)
        T[(size_t)(bn + y + i) * DM + bk + x] =
            __float2half_rn(tile[x][y + i] * WSCALE);
}

// ---------------------------------------------------------------------------
// fp32 small GEMM (weight-prep only): C[M,64] = A[M,1024] @ W[1024,64] + bias
// ---------------------------------------------------------------------------
__global__ __launch_bounds__(256) void sgemm_small(
    const float* __restrict__ A, const float* __restrict__ W,
    const float* __restrict__ bias, float* __restrict__ C)
{
    __shared__ __align__(16) float As[16][64];
    __shared__ __align__(16) float Bs[16][64];
    const int tid  = threadIdx.x;
    const int brow = blockIdx.y * 64;
    const int arow = tid >> 2;
    const int akof = (tid & 3) * 4;
    const int bkr  = tid >> 4;
    const int bc4  = (tid & 15) * 4;
    const int trow = (tid >> 4) * 4;
    const int tcol = (tid & 15) * 4;

    float acc[4][4];
    #pragma unroll
    for (int i = 0; i < 4; i++)
        #pragma unroll
        for (int j = 0; j < 4; j++) acc[i][j] = 0.f;

    const float* Ab = A + (size_t)(brow + arow) * DM + akof;
    const float* Wb = W + (size_t)bkr * HG + bc4;

    for (int k0 = 0; k0 < DM; k0 += 16) {
        float4 av = *(const float4*)(Ab + k0);
        As[akof + 0][arow] = av.x;
        As[akof + 1][arow] = av.y;
        As[akof + 2][arow] = av.z;
        As[akof + 3][arow] = av.w;
        float4 bv = *(const float4*)(Wb + (size_t)k0 * HG);
        *(float4*)&Bs[bkr][bc4] = bv;
        __syncthreads();
        #pragma unroll
        for (int kk = 0; kk < 16; kk++) {
            float4 a0 = *(const float4*)&As[kk][trow];
            float4 b0 = *(const float4*)&Bs[kk][tcol];
            float ar[4] = {a0.x, a0.y, a0.z, a0.w};
            float br[4] = {b0.x, b0.y, b0.z, b0.w};
            #pragma unroll
            for (int i = 0; i < 4; i++)
                #pragma unroll
                for (int j = 0; j < 4; j++)
                    acc[i][j] = fmaf(ar[i], br[j], acc[i][j]);
        }
        __syncthreads();
    }
    #pragma unroll
    for (int i = 0; i < 4; i++)
        #pragma unroll
        for (int j = 0; j < 4; j++)
            C[(size_t)(brow + trow + i) * HG + tcol + j] = acc[i][j] + bias[tcol + j];
}

// ---------------------------------------------------------------------------
// combined bias: b1[j] = bqa[j] + sum_i bq[i] * Wqa[i][j]
// ---------------------------------------------------------------------------
__global__ void bias_comb(const float* __restrict__ bq,
                          const float* __restrict__ Wqa,
                          const float* __restrict__ bqa,
                          float* __restrict__ b1)
{
    __shared__ float part[4][HG];
    const int j = threadIdx.x & 63;
    const int p = threadIdx.x >> 6;
    float s = 0.f;
    for (int i = p * 256; i < (p + 1) * 256; ++i)
        s = fmaf(bq[i], Wqa[(size_t)i * HG + j], s);
    part[p][j] = s;
    __syncthreads();
    if (p == 0)
        b1[j] = bqa[j] + ((part[0][j] + part[1][j]) + (part[2][j] + part[3][j]));
}

__global__ __launch_bounds__(256) void zero2(float* __restrict__ a,
                                             float* __restrict__ b)
{
    const int i = blockIdx.x * 256 + threadIdx.x;
    a[i] = 0.f; b[i] = 0.f;
}

// ---------------------------------------------------------------------------
// Softmax over n per (b, col)
// ---------------------------------------------------------------------------
__global__ __launch_bounds__(256) void softmax_n(
    float* __restrict__ s, const float* __restrict__ mask)
{
    const int b   = blockIdx.x / HG;
    const int col = blockIdx.x % HG;
    const int tid = threadIdx.x;
    float* base = s + (size_t)b * SEQ * HG + col;
    const float* mb = mask + (size_t)b * SEQ;

    float vals[16];
    float mx = -1e30f;
    #pragma unroll
    for (int i = 0; i < 16; i++) {
        const int n = tid + i * 256;
        float v = base[(size_t)n * HG] * INV_SCALE + mb[n];
        vals[i] = v;
        mx = fmaxf(mx, v);
    }
    __shared__ float red[256];
    red[tid] = mx; __syncthreads();
    for (int st = 128; st > 0; st >>= 1) {
        if (tid < st) red[tid] = fmaxf(red[tid], red[tid + st]);
        __syncthreads();
    }
    mx = red[0]; __syncthreads();
    float sum = 0.f;
    #pragma unroll
    for (int i = 0; i < 16; i++) { vals[i] = __expf(vals[i] - mx); sum += vals[i]; }
    red[tid] = sum; __syncthreads();
    for (int st = 128; st > 0; st >>= 1) {
        if (tid < st) red[tid] += red[tid + st];
        __syncthreads();
    }
    const float rs = 1.f / red[0];
    #pragma unroll
    for (int i = 0; i < 16; i++) {
        const int n = tid + i * 256;
        base[(size_t)n * HG] = vals[i] * rs;
    }
}

// ---------------------------------------------------------------------------
// gsum, fp32 x: g[b,h,d,g] += sum_{chunk} w[b,n,h,g] * x[b,n,h*64+d]
// ---------------------------------------------------------------------------
__global__ __launch_bounds__(256) void gsum_f(
    const float* __restrict__ x, const float* __restrict__ w,
    float* __restrict__ out)
{
    const int b = blockIdx.x / NH;
    const int h = blockIdx.x % NH;
    const int n0 = blockIdx.y * 256;
    const int g = threadIdx.x >> 6;
    const int d = threadIdx.x & 63;
    const float* xp = x + ((size_t)b * SEQ + n0) * DM + h * HD + d;
    const float* wp = w + ((size_t)b * SEQ + n0) * HG + h * NG + g;
    float a0 = 0.f, a1 = 0.f, a2 = 0.f, a3 = 0.f;
    #pragma unroll 4
    for (int n = 0; n < 256; n += 4) {
        a0 = fmaf(xp[(size_t)(n + 0) * DM], wp[(size_t)(n + 0) * HG], a0);
        a1 = fmaf(xp[(size_t)(n + 1) * DM], wp[(size_t)(n + 1) * HG], a1);
        a2 = fmaf(xp[(size_t)(n + 2) * DM], wp[(size_t)(n + 2) * HG], a2);
        a3 = fmaf(xp[(size_t)(n + 3) * DM], wp[(size_t)(n + 3) * HG], a3);
    }
    atomicAdd(&out[(((size_t)(b * NH + h) * HD) + d) * NG + g],
              (a0 + a1) + (a2 + a3));
}

// gsum, fp16 x
__global__ __launch_bounds__(256) void gsum_h(
    const __half* __restrict__ x, const float* __restrict__ w,
    float* __restrict__ out)
{
    const int b = blockIdx.x / NH;
    const int h = blockIdx.x % NH;
    const int n0 = blockIdx.y * 256;
    const int g = threadIdx.x >> 6;
    const int d = threadIdx.x & 63;
    const __half* xp = x + ((size_t)b * SEQ + n0) * DM + h * HD + d;
    const float* wp = w + ((size_t)b * SEQ + n0) * HG + h * NG + g;
    float a0 = 0.f, a1 = 0.f, a2 = 0.f, a3 = 0.f;
    #pragma unroll 4
    for (int n = 0; n < 256; n += 4) {
        a0 = fmaf(__half2float(xp[(size_t)(n + 0) * DM]), wp[(size_t)(n + 0) * HG], a0);
        a1 = fmaf(__half2float(xp[(size_t)(n + 1) * DM]), wp[(size_t)(n + 1) * HG], a1);
        a2 = fmaf(__half2float(xp[(size_t)(n + 2) * DM]), wp[(size_t)(n + 2) * HG], a2);
        a3 = fmaf(__half2float(xp[(size_t)(n + 3) * DM]), wp[(size_t)(n + 3) * HG], a3);
    }
    atomicAdd(&out[(((size_t)(b * NH + h) * HD) + d) * NG + g],
              (a0 + a1) + (a2 + a3));
}

// ---------------------------------------------------------------------------
// out[m, hd] = max_g x[m,hd] * gm[b,h,d,g]   (fp16 in, fp16 out)
// ---------------------------------------------------------------------------
__global__ __launch_bounds__(256) void maxg_hh(
    const __half* __restrict__ x, const float* __restrict__ gm,
    __half* __restrict__ out)
{
    const size_t i = (size_t)blockIdx.x * 256 + threadIdx.x;
    const int hd = (int)(i & (DM - 1));
    const size_t m = i >> 10;
    const int b = (int)(m >> 12);
    const int h = hd >> 6;
    const int d = hd & 63;
    const float4 gv = *(const float4*)&gm[(((size_t)(b * NH + h) * HD) + d) * NG];
    const float xv = __half2float(x[i]);
    out[i] = __float2half_rn(
        fmaxf(fmaxf(xv * gv.x, xv * gv.y), fmaxf(xv * gv.z, xv * gv.w)));
}

// ---------------------------------------------------------------------------
// Launch
// ---------------------------------------------------------------------------
extern "C" void kernel_launch(void* const* d_in, const int* in_sizes, int n_in,
                              void* d_out, int out_size)
{
    const float* hs   = (const float*)d_in[0];
    const float* mask = (const float*)d_in[1];
    const float* Wq   = (const float*)d_in[2];
    const float* bq   = (const float*)d_in[3];
    const float* Wqa  = (const float*)d_in[4];
    const float* bqa  = (const float*)d_in[5];
    const float* Wk   = (const float*)d_in[6];
    const float* bk   = (const float*)d_in[7];
    const float* Wka  = (const float*)d_in[8];
    const float* bka  = (const float*)d_in[9];
    const float* Wv   = (const float*)d_in[10];
    const float* bv   = (const float*)d_in[11];
    const float* Wt   = (const float*)d_in[12];
    const float* bt   = (const float*)d_in[13];
    float* out = (float*)d_out;

    float *q, *s1, *s2, *gq, *gk, *b1, *zv;
    __half *kh, *vh, *ah, *wh, *ws1, *ws2;
    cudaGetSymbolAddress((void**)&q,   g_q);
    cudaGetSymbolAddress((void**)&s1,  g_s1);
    cudaGetSymbolAddress((void**)&s2,  g_s2);
    cudaGetSymbolAddress((void**)&gq,  g_gq);
    cudaGetSymbolAddress((void**)&gk,  g_gk);
    cudaGetSymbolAddress((void**)&b1,  g_b1);
    cudaGetSymbolAddress((void**)&zv,  g_zero);
    cudaGetSymbolAddress((void**)&kh,  g_kh);
    cudaGetSymbolAddress((void**)&vh,  g_vh);
    cudaGetSymbolAddress((void**)&ah,  g_ah);
    cudaGetSymbolAddress((void**)&wh,  g_wh);
    cudaGetSymbolAddress((void**)&ws1, g_ws1);
    cudaGetSymbolAddress((void**)&ws2, g_ws2);

    cudaFuncSetAttribute(gemm_qkv,  cudaFuncAttributeMaxDynamicSharedMemorySize, SMEM_BIG);
    cudaFuncSetAttribute(gemm_hmma, cudaFuncAttributeMaxDynamicSharedMemorySize, SMEM_BIG);
    cudaFuncSetAttribute(gemm_n64,  cudaFuncAttributeMaxDynamicSharedMemorySize, SMEM_N64);

    const size_t WSZ = (size_t)DM * DM;
    dim3 bW(32, 8);
    dim3 gW4(DM / 32, DM / 32, 4);
    dim3 gW64(HG / 32, DM / 32);
    dim3 gQKV(3 * DM / 128, MROWS / 128);    // (24, 256)
    dim3 gG(DM / 128, MROWS / 128);          // (8, 256)
    dim3 gGs(BATCH * NH, SEQ / 256);         // (128, 16)

    // --- prep ---
    zero2<<<(BATCH * NH * HD * NG) / 256, 256>>>(gq, gk);
    wconv4<<<gW4, bW>>>(Wq, Wk, Wv, Wt, wh);
    sgemm_small<<<dim3(1, DM / 64), 256>>>(Wq, Wqa, zv, s2);   // WqWqa fp32 tmp
    wconv_t<<<gW64, bW>>>(s2, ws1, HG);
    bias_comb<<<1, 256>>>(bq, Wqa, bqa, b1);
    wconv_t<<<gW64, bW>>>(Wka, ws2, HG);
    tofp16<<<(MROWS * DM / 4) / 256, 256>>>((const float4*)hs, (__half2*)ah);

    // --- fused q,k,v projection (q fp32; k,v fp16) ---
    gemm_qkv<<<gQKV, 256, SMEM_BIG>>>(ah, wh, bq, bk, bv, q, kh, vh);

    // --- q scores -> softmax -> gq -> qk(fp16) ---
    gemm_n64<<<MROWS / 128, 256, SMEM_N64>>>(ah, ws1, b1, nullptr, s1);
    softmax_n<<<BATCH * HG, 256>>>(s1, mask);
    gsum_f<<<gGs, 256>>>(q, s1, gq);
    maxg_hh<<<(MROWS * DM) / 256, 256>>>(kh, gq, ah);

    // --- k scores -> gk -> u(fp16) ---
    gemm_n64<<<MROWS / 128, 256, SMEM_N64>>>(ah, ws2, bka, mask, s2);
    gsum_h<<<gGs, 256>>>(kh, s2, gk);
    maxg_hh<<<(MROWS * DM) / 256, 256>>>(vh, gk, ah);

    // --- out = u @ Wt + bt + q ---
    gemm_hmma<<<gG, 256, SMEM_BIG>>>(ah, wh + 3 * WSZ, bt, q, out);
}

// round 7
// speedup vs baseline: 4.9121x; 1.0236x over previous
#include <cuda_runtime.h>
#include <cuda_fp16.h>
#include <cstdint>

// Problem constants
#define BATCH 8
#define SEQ   4096
#define DM    1024
#define NH    16
#define NG    4
#define HD    64
#define HG    (NH*NG)          // 64
#define MROWS (BATCH*SEQ)      // 32768
#define INV_SCALE 0.125f       // 1/sqrt(64)
#define WSCALE 1024.0f
#define WUNSCALE (1.0f/1024.0f)
#define GSZ (BATCH*NH*HD*NG)   // 32768

// ---------------------------------------------------------------------------
// Scratch (device globals)
// ---------------------------------------------------------------------------
__device__ float g_s1[MROWS * HG];              // exp(q-scores)
__device__ float g_s2[MROWS * HG];              // ksc; WqWqa fp32 tmp during prep
__device__ float g_gq[GSZ];
__device__ float g_gk[GSZ];
__device__ float g_cs[BATCH * HG];              // col sums of exp
__device__ float g_b1[HG];                      // bq@Wqa + bqa
__device__ float g_zero[HG];
__device__ __align__(256) __half g_qh[MROWS * DM];
__device__ __align__(256) __half g_kh[MROWS * DM];
__device__ __align__(256) __half g_vh[MROWS * DM];
__device__ __align__(256) __half g_ah[MROWS * DM];        // hs -> qk -> u
__device__ __align__(256) __half g_wcat[(3 * DM + 128) * DM]; // WqT|WkT|WvT|ws1pad
__device__ __align__(256) __half g_wt[DM * DM];           // WtT
__device__ __align__(256) __half g_ws2[HG * DM];          // WkaT

// ---------------------------------------------------------------------------
// PTX helpers (plain sm_103-safe)
// ---------------------------------------------------------------------------
__device__ __forceinline__ uint32_t smem_u32(const void* p) {
    uint32_t a;
    asm("{ .reg .u64 t; cvta.to.shared.u64 t, %1; cvt.u32.u64 %0, t; }"
        : "=r"(a) : "l"(p));
    return a;
}
#define CP_ASYNC16(s, g) \
    asm volatile("cp.async.cg.shared.global [%0], [%1], 16;" :: "r"(s), "l"(g))
#define CP_COMMIT() asm volatile("cp.async.commit_group;" ::: "memory")
#define CP_WAIT(n)  asm volatile("cp.async.wait_group %0;" :: "n"(n) : "memory")
#define LDMX4(r, addr) \
    asm volatile("ldmatrix.sync.aligned.m8n8.x4.shared.b16 {%0,%1,%2,%3}, [%4];" \
        : "=r"((r)[0]), "=r"((r)[1]), "=r"((r)[2]), "=r"((r)[3]) : "r"(addr))
#define MMA_F16(d, a, b0, b1) \
    asm volatile("mma.sync.aligned.m16n8k16.row.col.f32.f16.f16.f32 " \
        "{%0,%1,%2,%3}, {%4,%5,%6,%7}, {%8,%9}, {%0,%1,%2,%3};" \
        : "+f"((d)[0]), "+f"((d)[1]), "+f"((d)[2]), "+f"((d)[3]) \
        : "r"((a)[0]), "r"((a)[1]), "r"((a)[2]), "r"((a)[3]), "r"(b0), "r"(b1))

#define SWZ(o) ((uint32_t)(o) ^ ((((uint32_t)(o)) >> 3) & 0x70))

#define BK 64
#define STG_BIG 32768
#define SMEM_BIG (2 * STG_BIG)

// ---------------------------------------------------------------------------
// Fused QKV+S1 GEMM.  B = [WqT|WkT|WvT|ws1pad] (3200 x 1024 fp16).
// which = blockIdx.x>>3: 0->qh fp16, 1->kh, 2->vh, 3->s1 = exp(score/8+mask).
// ---------------------------------------------------------------------------
__global__ __launch_bounds__(256, 2) void gemm_qkvs(
    const __half* __restrict__ A, const __half* __restrict__ B,
    const float* __restrict__ bq, const float* __restrict__ bk,
    const float* __restrict__ bv, const float* __restrict__ b1,
    const float* __restrict__ mask,
    __half* __restrict__ Q, __half* __restrict__ K, __half* __restrict__ V,
    float* __restrict__ S1)
{
    extern __shared__ char smem[];
    const uint32_t sbase = smem_u32(smem);
    const int tid  = threadIdx.x;
    const int lane = tid & 31;
    const int wid  = tid >> 5;
    const int wm   = wid & 3;
    const int wn   = wid >> 2;
    const int brow = blockIdx.y * 128;
    const int bcol = blockIdx.x * 128;
    const int which = blockIdx.x >> 3;           // 0..3
    const int bcl   = bcol & (DM - 1);
    const float* bias = which == 0 ? bq : which == 1 ? bk : which == 2 ? bv : b1;

    const int lrow  = tid >> 1;
    const int lhalf = tid & 1;
    const __half* gA = A + (size_t)(brow + lrow) * DM + lhalf * 32;
    const __half* gB = B + (size_t)(bcol + lrow) * DM + lhalf * 32;
    uint32_t soff[4];
    #pragma unroll
    for (int i = 0; i < 4; ++i)
        soff[i] = SWZ(lrow * 128 + lhalf * 64 + i * 16);

    float acc[2][8][4];
    #pragma unroll
    for (int mi = 0; mi < 2; ++mi)
        #pragma unroll
        for (int nt = 0; nt < 8; ++nt)
            #pragma unroll
            for (int r = 0; r < 4; ++r) acc[mi][nt][r] = 0.f;

    const int frow = lane & 15;
    const int fcol = (lane >> 4) << 4;

    {
        #pragma unroll
        for (int i = 0; i < 4; ++i) {
            CP_ASYNC16(sbase +         soff[i], gA + i * 8);
            CP_ASYNC16(sbase + 16384 + soff[i], gB + i * 8);
        }
        CP_COMMIT();
    }

    #pragma unroll 1
    for (int c = 0; c < 16; ++c) {
        const int s = c & 1;
        if (c + 1 < 16) {
            const uint32_t sb = sbase + ((c + 1) & 1) * STG_BIG;
            const size_t ko = (size_t)(c + 1) * BK;
            #pragma unroll
            for (int i = 0; i < 4; ++i) {
                CP_ASYNC16(sb +         soff[i], gA + ko + i * 8);
                CP_ASYNC16(sb + 16384 + soff[i], gB + ko + i * 8);
            }
            CP_COMMIT();
            CP_WAIT(1);
        } else {
            CP_WAIT(0);
        }
        __syncthreads();

        const uint32_t stg = sbase + s * STG_BIG;
        #pragma unroll
        for (int ks = 0; ks < 4; ++ks) {
            const uint32_t kb = ks * 32 + fcol;
            uint32_t a_r[2][4];
            #pragma unroll
            for (int mi = 0; mi < 2; ++mi) {
                const uint32_t o = SWZ((wm * 32 + mi * 16 + frow) * 128 + kb);
                LDMX4(a_r[mi], stg + o);
            }
            uint32_t b_r[4][4];
            #pragma unroll
            for (int nt2 = 0; nt2 < 4; ++nt2) {
                const uint32_t o = SWZ((wn * 64 + nt2 * 16 + frow) * 128 + kb);
                LDMX4(b_r[nt2], stg + 16384 + o);
            }
            #pragma unroll
            for (int mi = 0; mi < 2; ++mi)
                #pragma unroll
                for (int nt = 0; nt < 8; ++nt)
                    MMA_F16(acc[mi][nt], a_r[mi], b_r[nt >> 1][nt & 1], b_r[nt >> 1][(nt & 1) + 2]);
        }
        __syncthreads();
    }

    const int er = brow + wm * 32 + (lane >> 2);
    const int ec = bcl + wn * 64 + (lane & 3) * 2;
    if (which < 3) {
        __half* Ch = which == 0 ? Q : which == 1 ? K : V;
        #pragma unroll
        for (int mi = 0; mi < 2; ++mi) {
            #pragma unroll
            for (int nt = 0; nt < 8; ++nt) {
                const int row = er + mi * 16;
                const int col = ec + nt * 8;
                const float b0 = bias[col], b1v = bias[col + 1];
                *(__half2*)(Ch + (size_t)row * DM + col) =
                    __floats2half2_rn(acc[mi][nt][0] * WUNSCALE + b0,
                                      acc[mi][nt][1] * WUNSCALE + b1v);
                *(__half2*)(Ch + (size_t)(row + 8) * DM + col) =
                    __floats2half2_rn(acc[mi][nt][2] * WUNSCALE + b0,
                                      acc[mi][nt][3] * WUNSCALE + b1v);
            }
        }
    } else if (wn == 0) {   // s1: cols 0..63 valid
        #pragma unroll
        for (int mi = 0; mi < 2; ++mi) {
            #pragma unroll
            for (int nt = 0; nt < 8; ++nt) {
                const int row = er + mi * 16;
                const int col = (wn * 64 + nt * 8 + (lane & 3) * 2);
                const float b0 = bias[col], b1v = bias[col + 1];
                const float m0 = mask[row], m1 = mask[row + 8];
                S1[(size_t)row * HG + col] =
                    __expf((acc[mi][nt][0] * WUNSCALE + b0) * INV_SCALE + m0);
                S1[(size_t)row * HG + col + 1] =
                    __expf((acc[mi][nt][1] * WUNSCALE + b1v) * INV_SCALE + m0);
                S1[(size_t)(row + 8) * HG + col] =
                    __expf((acc[mi][nt][2] * WUNSCALE + b0) * INV_SCALE + m1);
                S1[(size_t)(row + 8) * HG + col + 1] =
                    __expf((acc[mi][nt][3] * WUNSCALE + b1v) * INV_SCALE + m1);
            }
        }
    }
}

// ---------------------------------------------------------------------------
// Final GEMM: out = u @ WtT + bt + q(fp16)
// ---------------------------------------------------------------------------
__global__ __launch_bounds__(256, 2) void gemm_hmma(
    const __half* __restrict__ A, const __half* __restrict__ B,
    const float* __restrict__ bias, const __half* __restrict__ addv,
    float* __restrict__ C)
{
    extern __shared__ char smem[];
    const uint32_t sbase = smem_u32(smem);
    const int tid  = threadIdx.x;
    const int lane = tid & 31;
    const int wid  = tid >> 5;
    const int wm   = wid & 3;
    const int wn   = wid >> 2;
    const int brow = blockIdx.y * 128;
    const int bcol = blockIdx.x * 128;

    const int lrow  = tid >> 1;
    const int lhalf = tid & 1;
    const __half* gA = A + (size_t)(brow + lrow) * DM + lhalf * 32;
    const __half* gB = B + (size_t)(bcol + lrow) * DM + lhalf * 32;
    uint32_t soff[4];
    #pragma unroll
    for (int i = 0; i < 4; ++i)
        soff[i] = SWZ(lrow * 128 + lhalf * 64 + i * 16);

    float acc[2][8][4];
    #pragma unroll
    for (int mi = 0; mi < 2; ++mi)
        #pragma unroll
        for (int nt = 0; nt < 8; ++nt)
            #pragma unroll
            for (int r = 0; r < 4; ++r) acc[mi][nt][r] = 0.f;

    const int frow = lane & 15;
    const int fcol = (lane >> 4) << 4;

    {
        #pragma unroll
        for (int i = 0; i < 4; ++i) {
            CP_ASYNC16(sbase +         soff[i], gA + i * 8);
            CP_ASYNC16(sbase + 16384 + soff[i], gB + i * 8);
        }
        CP_COMMIT();
    }

    #pragma unroll 1
    for (int c = 0; c < 16; ++c) {
        const int s = c & 1;
        if (c + 1 < 16) {
            const uint32_t sb = sbase + ((c + 1) & 1) * STG_BIG;
            const size_t ko = (size_t)(c + 1) * BK;
            #pragma unroll
            for (int i = 0; i < 4; ++i) {
                CP_ASYNC16(sb +         soff[i], gA + ko + i * 8);
                CP_ASYNC16(sb + 16384 + soff[i], gB + ko + i * 8);
            }
            CP_COMMIT();
            CP_WAIT(1);
        } else {
            CP_WAIT(0);
        }
        __syncthreads();

        const uint32_t stg = sbase + s * STG_BIG;
        #pragma unroll
        for (int ks = 0; ks < 4; ++ks) {
            const uint32_t kb = ks * 32 + fcol;
            uint32_t a_r[2][4];
            #pragma unroll
            for (int mi = 0; mi < 2; ++mi) {
                const uint32_t o = SWZ((wm * 32 + mi * 16 + frow) * 128 + kb);
                LDMX4(a_r[mi], stg + o);
            }
            uint32_t b_r[4][4];
            #pragma unroll
            for (int nt2 = 0; nt2 < 4; ++nt2) {
                const uint32_t o = SWZ((wn * 64 + nt2 * 16 + frow) * 128 + kb);
                LDMX4(b_r[nt2], stg + 16384 + o);
            }
            #pragma unroll
            for (int mi = 0; mi < 2; ++mi)
                #pragma unroll
                for (int nt = 0; nt < 8; ++nt)
                    MMA_F16(acc[mi][nt], a_r[mi], b_r[nt >> 1][nt & 1], b_r[nt >> 1][(nt & 1) + 2]);
        }
        __syncthreads();
    }

    const int er = brow + wm * 32 + (lane >> 2);
    const int ec = bcol + wn * 64 + (lane & 3) * 2;
    #pragma unroll
    for (int mi = 0; mi < 2; ++mi) {
        #pragma unroll
        for (int nt = 0; nt < 8; ++nt) {
            const int row = er + mi * 16;
            const int col = ec + nt * 8;
            const float b0 = bias[col], b1v = bias[col + 1];
            const __half2 a0 = *(const __half2*)(addv + (size_t)row * DM + col);
            const __half2 a1 = *(const __half2*)(addv + (size_t)(row + 8) * DM + col);
            const float2 f0 = __half22float2(a0);
            const float2 f1 = __half22float2(a1);
            *(float2*)(C + (size_t)row * DM + col) = make_float2(
                acc[mi][nt][0] * WUNSCALE + b0 + f0.x,
                acc[mi][nt][1] * WUNSCALE + b1v + f0.y);
            *(float2*)(C + (size_t)(row + 8) * DM + col) = make_float2(
                acc[mi][nt][2] * WUNSCALE + b0 + f1.x,
                acc[mi][nt][3] * WUNSCALE + b1v + f1.y);
        }
    }
}

// ---------------------------------------------------------------------------
// N=64 HMMA GEMM: ksc = (qk @ WkaT + bka)/8 + mask
// ---------------------------------------------------------------------------
#define STG_N64 24576
#define SMEM_N64 (2 * STG_N64)

__global__ __launch_bounds__(256, 2) void gemm_n64(
    const __half* __restrict__ A, const __half* __restrict__ B,
    const float* __restrict__ bias, const float* __restrict__ mask,
    float* __restrict__ C)
{
    extern __shared__ char smem[];
    const uint32_t sbase = smem_u32(smem);
    const int tid  = threadIdx.x;
    const int lane = tid & 31;
    const int wid  = tid >> 5;
    const int wm   = wid & 3;
    const int wn   = wid >> 2;
    const int brow = blockIdx.x * 128;

    const int lrow  = tid >> 1;
    const int lhalf = tid & 1;
    const __half* gA = A + (size_t)(brow + lrow) * DM + lhalf * 32;
    uint32_t aoff[4];
    #pragma unroll
    for (int i = 0; i < 4; ++i)
        aoff[i] = SWZ(lrow * 128 + lhalf * 64 + i * 16);
    const int  brw   = (tid & 127) >> 1;
    const int  bhalf = tid & 1;
    const bool bldr  = tid < 128;
    const __half* gB = B + (size_t)brw * DM + bhalf * 32;
    uint32_t boff[4];
    #pragma unroll
    for (int i = 0; i < 4; ++i)
        boff[i] = SWZ(brw * 128 + bhalf * 64 + i * 16);

    float acc[2][4][4];
    #pragma unroll
    for (int mi = 0; mi < 2; ++mi)
        #pragma unroll
        for (int nt = 0; nt < 4; ++nt)
            #pragma unroll
            for (int r = 0; r < 4; ++r) acc[mi][nt][r] = 0.f;

    const int frow = lane & 15;
    const int fcol = (lane >> 4) << 4;

    {
        #pragma unroll
        for (int i = 0; i < 4; ++i) {
            CP_ASYNC16(sbase + aoff[i], gA + i * 8);
            if (bldr) CP_ASYNC16(sbase + 16384 + boff[i], gB + i * 8);
        }
        CP_COMMIT();
    }

    #pragma unroll 1
    for (int c = 0; c < 16; ++c) {
        const int s = c & 1;
        if (c + 1 < 16) {
            const uint32_t sb = sbase + ((c + 1) & 1) * STG_N64;
            const size_t ko = (size_t)(c + 1) * BK;
            #pragma unroll
            for (int i = 0; i < 4; ++i) {
                CP_ASYNC16(sb + aoff[i], gA + ko + i * 8);
                if (bldr) CP_ASYNC16(sb + 16384 + boff[i], gB + ko + i * 8);
            }
            CP_COMMIT();
            CP_WAIT(1);
        } else {
            CP_WAIT(0);
        }
        __syncthreads();

        const uint32_t stg = sbase + s * STG_N64;
        #pragma unroll
        for (int ks = 0; ks < 4; ++ks) {
            const uint32_t kb = ks * 32 + fcol;
            uint32_t a_r[2][4];
            #pragma unroll
            for (int mi = 0; mi < 2; ++mi) {
                const uint32_t o = SWZ((wm * 32 + mi * 16 + frow) * 128 + kb);
                LDMX4(a_r[mi], stg + o);
            }
            uint32_t b_r[2][4];
            #pragma unroll
            for (int nt2 = 0; nt2 < 2; ++nt2) {
                const uint32_t o = SWZ((wn * 32 + nt2 * 16 + frow) * 128 + kb);
                LDMX4(b_r[nt2], stg + 16384 + o);
            }
            #pragma unroll
            for (int mi = 0; mi < 2; ++mi)
                #pragma unroll
                for (int nt = 0; nt < 4; ++nt)
                    MMA_F16(acc[mi][nt], a_r[mi], b_r[nt >> 1][nt & 1], b_r[nt >> 1][(nt & 1) + 2]);
        }
        __syncthreads();
    }

    const int er = brow + wm * 32 + (lane >> 2);
    const int ec = wn * 32 + (lane & 3) * 2;
    #pragma unroll
    for (int mi = 0; mi < 2; ++mi) {
        #pragma unroll
        for (int nt = 0; nt < 4; ++nt) {
            const int row = er + mi * 16;
            const int col = ec + nt * 8;
            const float b0 = bias[col], b1v = bias[col + 1];
            const float m0 = mask[row], m1 = mask[row + 8];
            *(float2*)(C + (size_t)row * HG + col) = make_float2(
                (acc[mi][nt][0] * WUNSCALE + b0) * INV_SCALE + m0,
                (acc[mi][nt][1] * WUNSCALE + b1v) * INV_SCALE + m0);
            *(float2*)(C + (size_t)(row + 8) * HG + col) = make_float2(
                (acc[mi][nt][2] * WUNSCALE + b0) * INV_SCALE + m1,
                (acc[mi][nt][3] * WUNSCALE + b1v) * INV_SCALE + m1);
        }
    }
}

// ---------------------------------------------------------------------------
// prep kernels
// ---------------------------------------------------------------------------
__global__ __launch_bounds__(256) void tofp16(
    const float4* __restrict__ x, __half2* __restrict__ o)
{
    const size_t i = (size_t)blockIdx.x * 256 + threadIdx.x;
    const float4 v = x[i];
    o[2 * i]     = __floats2half2_rn(v.x, v.y);
    o[2 * i + 1] = __floats2half2_rn(v.z, v.w);
}

__global__ __launch_bounds__(256) void wconv4(
    const float* __restrict__ W0, const float* __restrict__ W1,
    const float* __restrict__ W2, const float* __restrict__ W3,
    __half* __restrict__ Tcat, __half* __restrict__ Twt)
{
    __shared__ float tile[32][33];
    const int z = blockIdx.z;
    const float* W = z == 0 ? W0 : z == 1 ? W1 : z == 2 ? W2 : W3;
    __half* Tz = z < 3 ? Tcat + (size_t)z * DM * DM : Twt;
    const int bn = blockIdx.x * 32;
    const int bk = blockIdx.y * 32;
    const int x = threadIdx.x;
    const int y = threadIdx.y;
    #pragma unroll
    for (int i = 0; i < 32; i += 8)
        tile[y + i][x] = W[(size_t)(bk + y + i) * DM + bn + x];
    __syncthreads();
    #pragma unroll
    for (int i = 0; i < 32; i += 8)
        Tz[(size_t)(bn + y + i) * DM + bk + x] =
            __float2half_rn(tile[x][y + i] * WSCALE);
}

__global__ __launch_bounds__(256) void wconv_t(
    const float* __restrict__ W, __half* __restrict__ T, int ncols)
{
    __shared__ float tile[32][33];
    const int bn = blockIdx.x * 32;
    const int bk = blockIdx.y * 32;
    const int x = threadIdx.x;
    const int y = threadIdx.y;
    #pragma unroll
    for (int i = 0; i < 32; i += 8)
        tile[y + i][x] = W[(size_t)(bk + y + i) * ncols + bn + x];
    __syncthreads();
    #pragma unroll
    for (int i = 0; i < 32; i += 8)
        T[(size_t)(bn + y + i) * DM + bk + x] =
            __float2half_rn(tile[x][y + i] * WSCALE);
}

__global__ __launch_bounds__(256) void sgemm_small(
    const float* __restrict__ A, const float* __restrict__ W,
    const float* __restrict__ bias, float* __restrict__ C)
{
    __shared__ __align__(16) float As[16][64];
    __shared__ __align__(16) float Bs[16][64];
    const int tid  = threadIdx.x;
    const int brow = blockIdx.y * 64;
    const int arow = tid >> 2;
    const int akof = (tid & 3) * 4;
    const int bkr  = tid >> 4;
    const int bc4  = (tid & 15) * 4;
    const int trow = (tid >> 4) * 4;
    const int tcol = (tid & 15) * 4;

    float acc[4][4];
    #pragma unroll
    for (int i = 0; i < 4; i++)
        #pragma unroll
        for (int j = 0; j < 4; j++) acc[i][j] = 0.f;

    const float* Ab = A + (size_t)(brow + arow) * DM + akof;
    const float* Wb = W + (size_t)bkr * HG + bc4;

    for (int k0 = 0; k0 < DM; k0 += 16) {
        float4 av = *(const float4*)(Ab + k0);
        As[akof + 0][arow] = av.x;
        As[akof + 1][arow] = av.y;
        As[akof + 2][arow] = av.z;
        As[akof + 3][arow] = av.w;
        float4 bv = *(const float4*)(Wb + (size_t)k0 * HG);
        *(float4*)&Bs[bkr][bc4] = bv;
        __syncthreads();
        #pragma unroll
        for (int kk = 0; kk < 16; kk++) {
            float4 a0 = *(const float4*)&As[kk][trow];
            float4 b0 = *(const float4*)&Bs[kk][tcol];
            float ar[4] = {a0.x, a0.y, a0.z, a0.w};
            float br[4] = {b0.x, b0.y, b0.z, b0.w};
            #pragma unroll
            for (int i = 0; i < 4; i++)
                #pragma unroll
                for (int j = 0; j < 4; j++)
                    acc[i][j] = fmaf(ar[i], br[j], acc[i][j]);
        }
        __syncthreads();
    }
    #pragma unroll
    for (int i = 0; i < 4; i++)
        #pragma unroll
        for (int j = 0; j < 4; j++)
            C[(size_t)(brow + trow + i) * HG + tcol + j] = acc[i][j] + bias[tcol + j];
}

__global__ void bias_comb(const float* __restrict__ bq,
                          const float* __restrict__ Wqa,
                          const float* __restrict__ bqa,
                          float* __restrict__ b1)
{
    __shared__ float part[4][HG];
    const int j = threadIdx.x & 63;
    const int p = threadIdx.x >> 6;
    float s = 0.f;
    for (int i = p * 256; i < (p + 1) * 256; ++i)
        s = fmaf(bq[i], Wqa[(size_t)i * HG + j], s);
    part[p][j] = s;
    __syncthreads();
    if (p == 0)
        b1[j] = bqa[j] + ((part[0][j] + part[1][j]) + (part[2][j] + part[3][j]));
}

// zero gq, gk, colsum, ws1 pad rows (64..127)
__global__ __launch_bounds__(256) void zero_misc(
    float* __restrict__ gq, float* __restrict__ gk,
    float* __restrict__ cs, uint32_t* __restrict__ pad)
{
    const int i = blockIdx.x * 256 + threadIdx.x;   // 0..32767
    gq[i] = 0.f; gk[i] = 0.f; pad[i] = 0u;
    if (i < BATCH * HG) cs[i] = 0.f;
}

// per-(b,col) sum of exp over n (coalesced)
__global__ __launch_bounds__(256) void sum_cols(
    const float* __restrict__ s, float* __restrict__ cs)
{
    const int b  = blockIdx.x;
    const int n0 = blockIdx.y * 256;
    const int c  = threadIdx.x & 63;
    const int rq = threadIdx.x >> 6;
    const float* base = s + ((size_t)b * SEQ + n0) * HG;
    float acc = 0.f;
    for (int n = rq; n < 256; n += 4)
        acc += base[(size_t)n * HG + c];
    __shared__ float part[4][HG];
    part[rq][c] = acc;
    __syncthreads();
    if (rq == 0)
        atomicAdd(&cs[b * HG + c],
                  (part[0][c] + part[1][c]) + (part[2][c] + part[3][c]));
}

// gq[i] /= colsum   (i = ((b*NH+h)*HD+d)*NG+g)
__global__ __launch_bounds__(256) void norm_gq(
    float* __restrict__ gq, const float* __restrict__ cs)
{
    const int i = blockIdx.x * 256 + threadIdx.x;
    const int g = i & 3;
    const int h = (i >> 8) & 15;
    const int b = i >> 12;
    gq[i] /= cs[b * HG + h * NG + g];
}

// ---------------------------------------------------------------------------
// gsum (fp16 x): g[b,h,d,g] += sum_{chunk} w[b,n,h,g] * x[b,n,h*64+d]
// ---------------------------------------------------------------------------
__global__ __launch_bounds__(256) void gsum_h(
    const __half* __restrict__ x, const float* __restrict__ w,
    float* __restrict__ out)
{
    const int b = blockIdx.x / NH;
    const int h = blockIdx.x % NH;
    const int n0 = blockIdx.y * 256;
    const int g = threadIdx.x >> 6;
    const int d = threadIdx.x & 63;
    const __half* xp = x + ((size_t)b * SEQ + n0) * DM + h * HD + d;
    const float* wp = w + ((size_t)b * SEQ + n0) * HG + h * NG + g;
    float a0 = 0.f, a1 = 0.f, a2 = 0.f, a3 = 0.f;
    #pragma unroll 4
    for (int n = 0; n < 256; n += 4) {
        a0 = fmaf(__half2float(xp[(size_t)(n + 0) * DM]), wp[(size_t)(n + 0) * HG], a0);
        a1 = fmaf(__half2float(xp[(size_t)(n + 1) * DM]), wp[(size_t)(n + 1) * HG], a1);
        a2 = fmaf(__half2float(xp[(size_t)(n + 2) * DM]), wp[(size_t)(n + 2) * HG], a2);
        a3 = fmaf(__half2float(xp[(size_t)(n + 3) * DM]), wp[(size_t)(n + 3) * HG], a3);
    }
    atomicAdd(&out[(((size_t)(b * NH + h) * HD) + d) * NG + g],
              (a0 + a1) + (a2 + a3));
}

// ---------------------------------------------------------------------------
// out[m,hd] = max_g x[m,hd] * gm[b,h,d,g]
// ---------------------------------------------------------------------------
__global__ __launch_bounds__(256) void maxg_hh(
    const __half* __restrict__ x, const float* __restrict__ gm,
    __half* __restrict__ out)
{
    const size_t i = (size_t)blockIdx.x * 256 + threadIdx.x;
    const int hd = (int)(i & (DM - 1));
    const size_t m = i >> 10;
    const int b = (int)(m >> 12);
    const int h = hd >> 6;
    const int d = hd & 63;
    const float4 gv = *(const float4*)&gm[(((size_t)(b * NH + h) * HD) + d) * NG];
    const float xv = __half2float(x[i]);
    out[i] = __float2half_rn(
        fmaxf(fmaxf(xv * gv.x, xv * gv.y), fmaxf(xv * gv.z, xv * gv.w)));
}

// ---------------------------------------------------------------------------
// Launch
// ---------------------------------------------------------------------------
extern "C" void kernel_launch(void* const* d_in, const int* in_sizes, int n_in,
                              void* d_out, int out_size)
{
    const float* hs   = (const float*)d_in[0];
    const float* mask = (const float*)d_in[1];
    const float* Wq   = (const float*)d_in[2];
    const float* bq   = (const float*)d_in[3];
    const float* Wqa  = (const float*)d_in[4];
    const float* bqa  = (const float*)d_in[5];
    const float* Wk   = (const float*)d_in[6];
    const float* bk   = (const float*)d_in[7];
    const float* Wka  = (const float*)d_in[8];
    const float* bka  = (const float*)d_in[9];
    const float* Wv   = (const float*)d_in[10];
    const float* bv   = (const float*)d_in[11];
    const float* Wt   = (const float*)d_in[12];
    const float* bt   = (const float*)d_in[13];
    float* out = (float*)d_out;

    float *s1, *s2, *gq, *gk, *cs, *b1, *zv;
    __half *qh, *kh, *vh, *ah, *wcat, *wt, *ws2;
    cudaGetSymbolAddress((void**)&s1,   g_s1);
    cudaGetSymbolAddress((void**)&s2,   g_s2);
    cudaGetSymbolAddress((void**)&gq,   g_gq);
    cudaGetSymbolAddress((void**)&gk,   g_gk);
    cudaGetSymbolAddress((void**)&cs,   g_cs);
    cudaGetSymbolAddress((void**)&b1,   g_b1);
    cudaGetSymbolAddress((void**)&zv,   g_zero);
    cudaGetSymbolAddress((void**)&qh,   g_qh);
    cudaGetSymbolAddress((void**)&kh,   g_kh);
    cudaGetSymbolAddress((void**)&vh,   g_vh);
    cudaGetSymbolAddress((void**)&ah,   g_ah);
    cudaGetSymbolAddress((void**)&wcat, g_wcat);
    cudaGetSymbolAddress((void**)&wt,   g_wt);
    cudaGetSymbolAddress((void**)&ws2,  g_ws2);

    cudaFuncSetAttribute(gemm_qkvs, cudaFuncAttributeMaxDynamicSharedMemorySize, SMEM_BIG);
    cudaFuncSetAttribute(gemm_hmma, cudaFuncAttributeMaxDynamicSharedMemorySize, SMEM_BIG);
    cudaFuncSetAttribute(gemm_n64,  cudaFuncAttributeMaxDynamicSharedMemorySize, SMEM_N64);

    const size_t WSZ = (size_t)DM * DM;
    __half* ws1 = wcat + 3 * WSZ;                 // rows 0..63 used, 64..127 pad
    uint32_t* pad = (uint32_t*)(wcat + 3 * WSZ + 64 * DM);

    dim3 bW(32, 8);

    // --- prep ---
    zero_misc<<<GSZ / 256, 256>>>(gq, gk, cs, pad);
    wconv4<<<dim3(DM / 32, DM / 32, 4), bW>>>(Wq, Wk, Wv, Wt, wcat, wt);
    sgemm_small<<<dim3(1, DM / 64), 256>>>(Wq, Wqa, zv, s2);   // WqWqa tmp
    wconv_t<<<dim3(HG / 32, DM / 32), bW>>>(s2, ws1, HG);
    bias_comb<<<1, 256>>>(bq, Wqa, bqa, b1);
    wconv_t<<<dim3(HG / 32, DM / 32), bW>>>(Wka, ws2, HG);
    tofp16<<<(MROWS * DM / 4) / 256, 256>>>((const float4*)hs, (__half2*)ah);

    // --- fused q,k,v,s1 projection ---
    gemm_qkvs<<<dim3(25, MROWS / 128), 256, SMEM_BIG>>>(
        ah, wcat, bq, bk, bv, b1, mask, qh, kh, vh, s1);

    // --- softmax-free q-attention: colsum -> gsum(exp) -> normalize -> qk ---
    sum_cols<<<dim3(BATCH, SEQ / 256), 256>>>(s1, cs);
    gsum_h<<<dim3(BATCH * NH, SEQ / 256), 256>>>(qh, s1, gq);
    norm_gq<<<GSZ / 256, 256>>>(gq, cs);
    maxg_hh<<<(MROWS * DM) / 256, 256>>>(kh, gq, ah);

    // --- k scores -> gk -> u ---
    gemm_n64<<<MROWS / 128, 256, SMEM_N64>>>(ah, ws2, bka, mask, s2);
    gsum_h<<<dim3(BATCH * NH, SEQ / 256), 256>>>(kh, s2, gk);
    maxg_hh<<<(MROWS * DM) / 256, 256>>>(vh, gk, ah);

    // --- out = u @ Wt + bt + q ---
    gemm_hmma<<<dim3(DM / 128, MROWS / 128), 256, SMEM_BIG>>>(ah, wt, bt, qh, out);
}

// round 8
// speedup vs baseline: 5.2782x; 1.0745x over previous
#include <cuda_runtime.h>
#include <cuda_fp16.h>
#include <cstdint>

// Problem constants
#define BATCH 8
#define SEQ   4096
#define DM    1024
#define NH    16
#define NG    4
#define HD    64
#define HG    (NH*NG)          // 64
#define MROWS (BATCH*SEQ)      // 32768
#define INV_SCALE 0.125f       // 1/sqrt(64)
#define WSCALE 1024.0f
#define WUNSCALE (1.0f/1024.0f)
#define GSZ (BATCH*NH*HD*NG)   // 32768

// ---------------------------------------------------------------------------
// Scratch (device globals)
// ---------------------------------------------------------------------------
__device__ float g_s1[MROWS * HG];              // exp(q-scores)
__device__ float g_s2[MROWS * HG];              // ksc; WqWqa fp32 tmp during prep
__device__ __align__(16) float g_gq[GSZ];
__device__ __align__(16) float g_gk[GSZ];
__device__ __align__(16) float g_cs[BATCH * HG];// col sums of exp
__device__ float g_b1[HG];                      // bq@Wqa + bqa
__device__ float g_zero[HG];
__device__ __align__(256) __half2 g_gmm1[BATCH * NH * HD];  // (gmax,gmin) of gq/cs
__device__ __align__(256) __half2 g_gmm2[BATCH * NH * HD];  // (gmax,gmin) of gk
__device__ __align__(256) __half g_qh[MROWS * DM];
__device__ __align__(256) __half g_kh[MROWS * DM];
__device__ __align__(256) __half g_vh[MROWS * DM];
__device__ __align__(256) __half g_ah[MROWS * DM];            // hs fp16
__device__ __align__(256) __half g_wcat[(3 * DM + 128) * DM]; // WqT|WkT|WvT|ws1pad
__device__ __align__(256) __half g_wt[DM * DM];               // WtT
__device__ __align__(256) __half g_ws2[HG * DM];              // WkaT

// ---------------------------------------------------------------------------
// PTX helpers (plain sm_103-safe)
// ---------------------------------------------------------------------------
__device__ __forceinline__ uint32_t smem_u32(const void* p) {
    uint32_t a;
    asm("{ .reg .u64 t; cvta.to.shared.u64 t, %1; cvt.u32.u64 %0, t; }"
        : "=r"(a) : "l"(p));
    return a;
}
#define CP_ASYNC16(s, g) \
    asm volatile("cp.async.cg.shared.global [%0], [%1], 16;" :: "r"(s), "l"(g))
#define CP_COMMIT() asm volatile("cp.async.commit_group;" ::: "memory")
#define CP_WAIT(n)  asm volatile("cp.async.wait_group %0;" :: "n"(n) : "memory")
#define LDMX4(r, addr) \
    asm volatile("ldmatrix.sync.aligned.m8n8.x4.shared.b16 {%0,%1,%2,%3}, [%4];" \
        : "=r"((r)[0]), "=r"((r)[1]), "=r"((r)[2]), "=r"((r)[3]) : "r"(addr))
#define MMA_F16(d, a, b0, b1) \
    asm volatile("mma.sync.aligned.m16n8k16.row.col.f32.f16.f16.f32 " \
        "{%0,%1,%2,%3}, {%4,%5,%6,%7}, {%8,%9}, {%0,%1,%2,%3};" \
        : "+f"((d)[0]), "+f"((d)[1]), "+f"((d)[2]), "+f"((d)[3]) \
        : "r"((a)[0]), "r"((a)[1]), "r"((a)[2]), "r"((a)[3]), "r"(b0), "r"(b1))

#define SWZ(o) ((uint32_t)(o) ^ ((((uint32_t)(o)) >> 3) & 0x70))

#define BK 64
#define STG_BIG 32768
#define SMEM_BIG (2 * STG_BIG)

// Apply max-trick to one uint4 (8 fp16) with 8 gmm half2 entries (m0,m1).
__device__ __forceinline__ uint4 maxg_apply(uint4 xv, uint4 m0, uint4 m1) {
    uint32_t out[4];
    const uint32_t* xw  = (const uint32_t*)&xv;
    const uint32_t* mw0 = (const uint32_t*)&m0;
    const uint32_t* mw1 = (const uint32_t*)&m1;
    #pragma unroll
    for (int j = 0; j < 4; ++j) {
        const uint32_t ga = (j < 2) ? mw0[2 * j]     : mw1[2 * j - 4];
        const uint32_t gb = (j < 2) ? mw0[2 * j + 1] : mw1[2 * j - 3];
        const __half2 x2 = *(const __half2*)&xw[j];
        const __half2 g0 = *(const __half2*)&ga;   // (gmax_d, gmin_d)
        const __half2 g1 = *(const __half2*)&gb;
        const float x0 = __low2float(x2), x1 = __high2float(x2);
        const float s0 = (x0 >= 0.f) ? __low2float(g0) : __high2float(g0);
        const float s1 = (x1 >= 0.f) ? __low2float(g1) : __high2float(g1);
        const __half2 r = __floats2half2_rn(x0 * s0, x1 * s1);
        out[j] = *(const uint32_t*)&r;
    }
    return *(const uint4*)out;
}

// ---------------------------------------------------------------------------
// Fused QKV+S1 GEMM (unchanged from R7).
// ---------------------------------------------------------------------------
__global__ __launch_bounds__(256, 2) void gemm_qkvs(
    const __half* __restrict__ A, const __half* __restrict__ B,
    const float* __restrict__ bq, const float* __restrict__ bk,
    const float* __restrict__ bv, const float* __restrict__ b1,
    const float* __restrict__ mask,
    __half* __restrict__ Q, __half* __restrict__ K, __half* __restrict__ V,
    float* __restrict__ S1)
{
    extern __shared__ char smem[];
    const uint32_t sbase = smem_u32(smem);
    const int tid  = threadIdx.x;
    const int lane = tid & 31;
    const int wid  = tid >> 5;
    const int wm   = wid & 3;
    const int wn   = wid >> 2;
    const int brow = blockIdx.y * 128;
    const int bcol = blockIdx.x * 128;
    const int which = blockIdx.x >> 3;
    const int bcl   = bcol & (DM - 1);
    const float* bias = which == 0 ? bq : which == 1 ? bk : which == 2 ? bv : b1;

    const int lrow  = tid >> 1;
    const int lhalf = tid & 1;
    const __half* gA = A + (size_t)(brow + lrow) * DM + lhalf * 32;
    const __half* gB = B + (size_t)(bcol + lrow) * DM + lhalf * 32;
    uint32_t soff[4];
    #pragma unroll
    for (int i = 0; i < 4; ++i)
        soff[i] = SWZ(lrow * 128 + lhalf * 64 + i * 16);

    float acc[2][8][4];
    #pragma unroll
    for (int mi = 0; mi < 2; ++mi)
        #pragma unroll
        for (int nt = 0; nt < 8; ++nt)
            #pragma unroll
            for (int r = 0; r < 4; ++r) acc[mi][nt][r] = 0.f;

    const int frow = lane & 15;
    const int fcol = (lane >> 4) << 4;

    {
        #pragma unroll
        for (int i = 0; i < 4; ++i) {
            CP_ASYNC16(sbase +         soff[i], gA + i * 8);
            CP_ASYNC16(sbase + 16384 + soff[i], gB + i * 8);
        }
        CP_COMMIT();
    }

    #pragma unroll 1
    for (int c = 0; c < 16; ++c) {
        const int s = c & 1;
        if (c + 1 < 16) {
            const uint32_t sb = sbase + ((c + 1) & 1) * STG_BIG;
            const size_t ko = (size_t)(c + 1) * BK;
            #pragma unroll
            for (int i = 0; i < 4; ++i) {
                CP_ASYNC16(sb +         soff[i], gA + ko + i * 8);
                CP_ASYNC16(sb + 16384 + soff[i], gB + ko + i * 8);
            }
            CP_COMMIT();
            CP_WAIT(1);
        } else {
            CP_WAIT(0);
        }
        __syncthreads();

        const uint32_t stg = sbase + s * STG_BIG;
        #pragma unroll
        for (int ks = 0; ks < 4; ++ks) {
            const uint32_t kb = ks * 32 + fcol;
            uint32_t a_r[2][4];
            #pragma unroll
            for (int mi = 0; mi < 2; ++mi) {
                const uint32_t o = SWZ((wm * 32 + mi * 16 + frow) * 128 + kb);
                LDMX4(a_r[mi], stg + o);
            }
            uint32_t b_r[4][4];
            #pragma unroll
            for (int nt2 = 0; nt2 < 4; ++nt2) {
                const uint32_t o = SWZ((wn * 64 + nt2 * 16 + frow) * 128 + kb);
                LDMX4(b_r[nt2], stg + 16384 + o);
            }
            #pragma unroll
            for (int mi = 0; mi < 2; ++mi)
                #pragma unroll
                for (int nt = 0; nt < 8; ++nt)
                    MMA_F16(acc[mi][nt], a_r[mi], b_r[nt >> 1][nt & 1], b_r[nt >> 1][(nt & 1) + 2]);
        }
        __syncthreads();
    }

    const int er = brow + wm * 32 + (lane >> 2);
    const int ec = bcl + wn * 64 + (lane & 3) * 2;
    if (which < 3) {
        __half* Ch = which == 0 ? Q : which == 1 ? K : V;
        #pragma unroll
        for (int mi = 0; mi < 2; ++mi) {
            #pragma unroll
            for (int nt = 0; nt < 8; ++nt) {
                const int row = er + mi * 16;
                const int col = ec + nt * 8;
                const float b0 = bias[col], b1v = bias[col + 1];
                *(__half2*)(Ch + (size_t)row * DM + col) =
                    __floats2half2_rn(acc[mi][nt][0] * WUNSCALE + b0,
                                      acc[mi][nt][1] * WUNSCALE + b1v);
                *(__half2*)(Ch + (size_t)(row + 8) * DM + col) =
                    __floats2half2_rn(acc[mi][nt][2] * WUNSCALE + b0,
                                      acc[mi][nt][3] * WUNSCALE + b1v);
            }
        }
    } else if (wn == 0) {
        #pragma unroll
        for (int mi = 0; mi < 2; ++mi) {
            #pragma unroll
            for (int nt = 0; nt < 8; ++nt) {
                const int row = er + mi * 16;
                const int col = (wn * 64 + nt * 8 + (lane & 3) * 2);
                const float b0 = bias[col], b1v = bias[col + 1];
                const float m0 = mask[row], m1 = mask[row + 8];
                S1[(size_t)row * HG + col] =
                    __expf((acc[mi][nt][0] * WUNSCALE + b0) * INV_SCALE + m0);
                S1[(size_t)row * HG + col + 1] =
                    __expf((acc[mi][nt][1] * WUNSCALE + b1v) * INV_SCALE + m0);
                S1[(size_t)(row + 8) * HG + col] =
                    __expf((acc[mi][nt][2] * WUNSCALE + b0) * INV_SCALE + m1);
                S1[(size_t)(row + 8) * HG + col + 1] =
                    __expf((acc[mi][nt][3] * WUNSCALE + b1v) * INV_SCALE + m1);
            }
        }
    }
}

// ---------------------------------------------------------------------------
// Final GEMM with fused u-computation: A[m,hd] = vh[m,hd] * sel(gmm2)
// out = u @ WtT + bt + qh
// ---------------------------------------------------------------------------
#define GMM_OFF (2 * STG_BIG)
#define SMEM_BIGF (2 * STG_BIG + 4096)

__global__ __launch_bounds__(256, 2) void gemm_hmma_f(
    const __half* __restrict__ X, const __half2* __restrict__ gmm,
    const __half* __restrict__ B,
    const float* __restrict__ bias, const __half* __restrict__ addv,
    float* __restrict__ C)
{
    extern __shared__ char smem[];
    const uint32_t sbase = smem_u32(smem);
    const int tid  = threadIdx.x;
    const int lane = tid & 31;
    const int wid  = tid >> 5;
    const int wm   = wid & 3;
    const int wn   = wid >> 2;
    const int brow = blockIdx.y * 128;
    const int bcol = blockIdx.x * 128;
    const int bb   = brow >> 12;

    const int lrow  = tid >> 1;
    const int lhalf = tid & 1;
    const __half* gX = X + (size_t)(brow + lrow) * DM + lhalf * 32;
    const __half* gB = B + (size_t)(bcol + lrow) * DM + lhalf * 32;
    uint32_t soff[4];
    #pragma unroll
    for (int i = 0; i < 4; ++i)
        soff[i] = SWZ(lrow * 128 + lhalf * 64 + i * 16);

    // one-time gmm slice load: 4KB = 256 x 16B
    *(uint4*)(smem + GMM_OFF + tid * 16) =
        ((const uint4*)(gmm + (size_t)bb * NH * HD))[tid];

    // prologue: B chunk 0
    {
        #pragma unroll
        for (int i = 0; i < 4; ++i)
            CP_ASYNC16(sbase + 16384 + soff[i], gB + i * 8);
        CP_COMMIT();
    }
    __syncthreads();   // gmm visible

    float acc[2][8][4];
    #pragma unroll
    for (int mi = 0; mi < 2; ++mi)
        #pragma unroll
        for (int nt = 0; nt < 8; ++nt)
            #pragma unroll
            for (int r = 0; r < 4; ++r) acc[mi][nt][r] = 0.f;

    const int frow = lane & 15;
    const int fcol = (lane >> 4) << 4;
    const uint32_t gmo = GMM_OFF + lhalf * 128;   // + c*256 + i*32 later

    #pragma unroll 1
    for (int c = 0; c < 16; ++c) {
        const int s = c & 1;
        if (c + 1 < 16) {
            const uint32_t sb = sbase + ((c + 1) & 1) * STG_BIG;
            const size_t ko = (size_t)(c + 1) * BK;
            #pragma unroll
            for (int i = 0; i < 4; ++i)
                CP_ASYNC16(sb + 16384 + soff[i], gB + ko + i * 8);
            CP_COMMIT();
            CP_WAIT(1);
        } else {
            CP_WAIT(0);
        }

        // fused A: load X, apply max-trick, STS
        {
            const __half* xp = gX + c * 64;
            const uint32_t go = gmo + c * 256;
            char* sA = smem + s * STG_BIG;
            #pragma unroll
            for (int i = 0; i < 4; ++i) {
                const uint4 xv = *(const uint4*)(xp + i * 8);
                const uint4 m0 = *(const uint4*)(smem + go + i * 32);
                const uint4 m1 = *(const uint4*)(smem + go + i * 32 + 16);
                *(uint4*)(sA + soff[i]) = maxg_apply(xv, m0, m1);
            }
        }
        __syncthreads();

        const uint32_t stg = sbase + s * STG_BIG;
        #pragma unroll
        for (int ks = 0; ks < 4; ++ks) {
            const uint32_t kb = ks * 32 + fcol;
            uint32_t a_r[2][4];
            #pragma unroll
            for (int mi = 0; mi < 2; ++mi) {
                const uint32_t o = SWZ((wm * 32 + mi * 16 + frow) * 128 + kb);
                LDMX4(a_r[mi], stg + o);
            }
            uint32_t b_r[4][4];
            #pragma unroll
            for (int nt2 = 0; nt2 < 4; ++nt2) {
                const uint32_t o = SWZ((wn * 64 + nt2 * 16 + frow) * 128 + kb);
                LDMX4(b_r[nt2], stg + 16384 + o);
            }
            #pragma unroll
            for (int mi = 0; mi < 2; ++mi)
                #pragma unroll
                for (int nt = 0; nt < 8; ++nt)
                    MMA_F16(acc[mi][nt], a_r[mi], b_r[nt >> 1][nt & 1], b_r[nt >> 1][(nt & 1) + 2]);
        }
        __syncthreads();
    }

    const int er = brow + wm * 32 + (lane >> 2);
    const int ec = bcol + wn * 64 + (lane & 3) * 2;
    #pragma unroll
    for (int mi = 0; mi < 2; ++mi) {
        #pragma unroll
        for (int nt = 0; nt < 8; ++nt) {
            const int row = er + mi * 16;
            const int col = ec + nt * 8;
            const float b0 = bias[col], b1v = bias[col + 1];
            const float2 f0 = __half22float2(*(const __half2*)(addv + (size_t)row * DM + col));
            const float2 f1 = __half22float2(*(const __half2*)(addv + (size_t)(row + 8) * DM + col));
            *(float2*)(C + (size_t)row * DM + col) = make_float2(
                acc[mi][nt][0] * WUNSCALE + b0 + f0.x,
                acc[mi][nt][1] * WUNSCALE + b1v + f0.y);
            *(float2*)(C + (size_t)(row + 8) * DM + col) = make_float2(
                acc[mi][nt][2] * WUNSCALE + b0 + f1.x,
                acc[mi][nt][3] * WUNSCALE + b1v + f1.y);
        }
    }
}

// ---------------------------------------------------------------------------
// N=64 GEMM with fused qk-computation: A = kh * sel(gmm1); ksc epilogue.
// ---------------------------------------------------------------------------
#define STG_N64 24576
#define GMM_OFF64 (2 * STG_N64)
#define SMEM_N64F (2 * STG_N64 + 4096)

__global__ __launch_bounds__(256, 2) void gemm_n64_f(
    const __half* __restrict__ X, const __half2* __restrict__ gmm,
    const __half* __restrict__ B,
    const float* __restrict__ bias, const float* __restrict__ mask,
    float* __restrict__ C)
{
    extern __shared__ char smem[];
    const uint32_t sbase = smem_u32(smem);
    const int tid  = threadIdx.x;
    const int lane = tid & 31;
    const int wid  = tid >> 5;
    const int wm   = wid & 3;
    const int wn   = wid >> 2;
    const int brow = blockIdx.x * 128;
    const int bb   = brow >> 12;

    const int lrow  = tid >> 1;
    const int lhalf = tid & 1;
    const __half* gX = X + (size_t)(brow + lrow) * DM + lhalf * 32;
    uint32_t aoff[4];
    #pragma unroll
    for (int i = 0; i < 4; ++i)
        aoff[i] = SWZ(lrow * 128 + lhalf * 64 + i * 16);
    const int  brw   = (tid & 127) >> 1;
    const int  bhalf = tid & 1;
    const bool bldr  = tid < 128;
    const __half* gB = B + (size_t)brw * DM + bhalf * 32;
    uint32_t boff[4];
    #pragma unroll
    for (int i = 0; i < 4; ++i)
        boff[i] = SWZ(brw * 128 + bhalf * 64 + i * 16);

    *(uint4*)(smem + GMM_OFF64 + tid * 16) =
        ((const uint4*)(gmm + (size_t)bb * NH * HD))[tid];

    {
        #pragma unroll
        for (int i = 0; i < 4; ++i)
            if (bldr) CP_ASYNC16(sbase + 16384 + boff[i], gB + i * 8);
        CP_COMMIT();
    }
    __syncthreads();

    float acc[2][4][4];
    #pragma unroll
    for (int mi = 0; mi < 2; ++mi)
        #pragma unroll
        for (int nt = 0; nt < 4; ++nt)
            #pragma unroll
            for (int r = 0; r < 4; ++r) acc[mi][nt][r] = 0.f;

    const int frow = lane & 15;
    const int fcol = (lane >> 4) << 4;
    const uint32_t gmo = GMM_OFF64 + lhalf * 128;

    #pragma unroll 1
    for (int c = 0; c < 16; ++c) {
        const int s = c & 1;
        if (c + 1 < 16) {
            const uint32_t sb = sbase + ((c + 1) & 1) * STG_N64;
            const size_t ko = (size_t)(c + 1) * BK;
            #pragma unroll
            for (int i = 0; i < 4; ++i)
                if (bldr) CP_ASYNC16(sb + 16384 + boff[i], gB + ko + i * 8);
            CP_COMMIT();
            CP_WAIT(1);
        } else {
            CP_WAIT(0);
        }

        {
            const __half* xp = gX + c * 64;
            const uint32_t go = gmo + c * 256;
            char* sA = smem + s * STG_N64;
            #pragma unroll
            for (int i = 0; i < 4; ++i) {
                const uint4 xv = *(const uint4*)(xp + i * 8);
                const uint4 m0 = *(const uint4*)(smem + go + i * 32);
                const uint4 m1 = *(const uint4*)(smem + go + i * 32 + 16);
                *(uint4*)(sA + aoff[i]) = maxg_apply(xv, m0, m1);
            }
        }
        __syncthreads();

        const uint32_t stg = sbase + s * STG_N64;
        #pragma unroll
        for (int ks = 0; ks < 4; ++ks) {
            const uint32_t kb = ks * 32 + fcol;
            uint32_t a_r[2][4];
            #pragma unroll
            for (int mi = 0; mi < 2; ++mi) {
                const uint32_t o = SWZ((wm * 32 + mi * 16 + frow) * 128 + kb);
                LDMX4(a_r[mi], stg + o);
            }
            uint32_t b_r[2][4];
            #pragma unroll
            for (int nt2 = 0; nt2 < 2; ++nt2) {
                const uint32_t o = SWZ((wn * 32 + nt2 * 16 + frow) * 128 + kb);
                LDMX4(b_r[nt2], stg + 16384 + o);
            }
            #pragma unroll
            for (int mi = 0; mi < 2; ++mi)
                #pragma unroll
                for (int nt = 0; nt < 4; ++nt)
                    MMA_F16(acc[mi][nt], a_r[mi], b_r[nt >> 1][nt & 1], b_r[nt >> 1][(nt & 1) + 2]);
        }
        __syncthreads();
    }

    const int er = brow + wm * 32 + (lane >> 2);
    const int ec = wn * 32 + (lane & 3) * 2;
    #pragma unroll
    for (int mi = 0; mi < 2; ++mi) {
        #pragma unroll
        for (int nt = 0; nt < 4; ++nt) {
            const int row = er + mi * 16;
            const int col = ec + nt * 8;
            const float b0 = bias[col], b1v = bias[col + 1];
            const float m0 = mask[row], m1 = mask[row + 8];
            *(float2*)(C + (size_t)row * HG + col) = make_float2(
                (acc[mi][nt][0] * WUNSCALE + b0) * INV_SCALE + m0,
                (acc[mi][nt][1] * WUNSCALE + b1v) * INV_SCALE + m0);
            *(float2*)(C + (size_t)(row + 8) * HG + col) = make_float2(
                (acc[mi][nt][2] * WUNSCALE + b0) * INV_SCALE + m1,
                (acc[mi][nt][3] * WUNSCALE + b1v) * INV_SCALE + m1);
        }
    }
}

// ---------------------------------------------------------------------------
// gminmax: gmm[b,h,d] = (max_g, min_g) of g[b,h,d,g] (optionally / cs[b,h*4+g])
// ---------------------------------------------------------------------------
__global__ __launch_bounds__(256) void gminmax(
    const float* __restrict__ g, const float* __restrict__ cs,
    __half2* __restrict__ gmm)
{
    const int i = blockIdx.x * 256 + threadIdx.x;   // (b*16+h)*64+d
    float4 v = ((const float4*)g)[i];
    if (cs) {
        const float4 c4 = ((const float4*)cs)[i >> 6];  // cs[b][h*4..h*4+3]
        v.x /= c4.x; v.y /= c4.y; v.z /= c4.z; v.w /= c4.w;
    }
    const float mx = fmaxf(fmaxf(v.x, v.y), fmaxf(v.z, v.w));
    const float mn = fminf(fminf(v.x, v.y), fminf(v.z, v.w));
    gmm[i] = __floats2half2_rn(mx, mn);
}

// ---------------------------------------------------------------------------
// prep kernels (unchanged)
// ---------------------------------------------------------------------------
__global__ __launch_bounds__(256) void tofp16(
    const float4* __restrict__ x, __half2* __restrict__ o)
{
    const size_t i = (size_t)blockIdx.x * 256 + threadIdx.x;
    const float4 v = x[i];
    o[2 * i]     = __floats2half2_rn(v.x, v.y);
    o[2 * i + 1] = __floats2half2_rn(v.z, v.w);
}

__global__ __launch_bounds__(256) void wconv4(
    const float* __restrict__ W0, const float* __restrict__ W1,
    const float* __restrict__ W2, const float* __restrict__ W3,
    __half* __restrict__ Tcat, __half* __restrict__ Twt)
{
    __shared__ float tile[32][33];
    const int z = blockIdx.z;
    const float* W = z == 0 ? W0 : z == 1 ? W1 : z == 2 ? W2 : W3;
    __half* Tz = z < 3 ? Tcat + (size_t)z * DM * DM : Twt;
    const int bn = blockIdx.x * 32;
    const int bk = blockIdx.y * 32;
    const int x = threadIdx.x;
    const int y = threadIdx.y;
    #pragma unroll
    for (int i = 0; i < 32; i += 8)
        tile[y + i][x] = W[(size_t)(bk + y + i) * DM + bn + x];
    __syncthreads();
    #pragma unroll
    for (int i = 0; i < 32; i += 8)
        Tz[(size_t)(bn + y + i) * DM + bk + x] =
            __float2half_rn(tile[x][y + i] * WSCALE);
}

__global__ __launch_bounds__(256) void wconv_t(
    const float* __restrict__ W, __half* __restrict__ T, int ncols)
{
    __shared__ float tile[32][33];
    const int bn = blockIdx.x * 32;
    const int bk = blockIdx.y * 32;
    const int x = threadIdx.x;
    const int y = threadIdx.y;
    #pragma unroll
    for (int i = 0; i < 32; i += 8)
        tile[y + i][x] = W[(size_t)(bk + y + i) * ncols + bn + x];
    __syncthreads();
    #pragma unroll
    for (int i = 0; i < 32; i += 8)
        T[(size_t)(bn + y + i) * DM + bk + x] =
            __float2half_rn(tile[x][y + i] * WSCALE);
}

__global__ __launch_bounds__(256) void sgemm_small(
    const float* __restrict__ A, const float* __restrict__ W,
    const float* __restrict__ bias, float* __restrict__ C)
{
    __shared__ __align__(16) float As[16][64];
    __shared__ __align__(16) float Bs[16][64];
    const int tid  = threadIdx.x;
    const int brow = blockIdx.y * 64;
    const int arow = tid >> 2;
    const int akof = (tid & 3) * 4;
    const int bkr  = tid >> 4;
    const int bc4  = (tid & 15) * 4;
    const int trow = (tid >> 4) * 4;
    const int tcol = (tid & 15) * 4;

    float acc[4][4];
    #pragma unroll
    for (int i = 0; i < 4; i++)
        #pragma unroll
        for (int j = 0; j < 4; j++) acc[i][j] = 0.f;

    const float* Ab = A + (size_t)(brow + arow) * DM + akof;
    const float* Wb = W + (size_t)bkr * HG + bc4;

    for (int k0 = 0; k0 < DM; k0 += 16) {
        float4 av = *(const float4*)(Ab + k0);
        As[akof + 0][arow] = av.x;
        As[akof + 1][arow] = av.y;
        As[akof + 2][arow] = av.z;
        As[akof + 3][arow] = av.w;
        float4 bv = *(const float4*)(Wb + (size_t)k0 * HG);
        *(float4*)&Bs[bkr][bc4] = bv;
        __syncthreads();
        #pragma unroll
        for (int kk = 0; kk < 16; kk++) {
            float4 a0 = *(const float4*)&As[kk][trow];
            float4 b0 = *(const float4*)&Bs[kk][tcol];
            float ar[4] = {a0.x, a0.y, a0.z, a0.w};
            float br[4] = {b0.x, b0.y, b0.z, b0.w};
            #pragma unroll
            for (int i = 0; i < 4; i++)
                #pragma unroll
                for (int j = 0; j < 4; j++)
                    acc[i][j] = fmaf(ar[i], br[j], acc[i][j]);
        }
        __syncthreads();
    }
    #pragma unroll
    for (int i = 0; i < 4; i++)
        #pragma unroll
        for (int j = 0; j < 4; j++)
            C[(size_t)(brow + trow + i) * HG + tcol + j] = acc[i][j] + bias[tcol + j];
}

__global__ void bias_comb(const float* __restrict__ bq,
                          const float* __restrict__ Wqa,
                          const float* __restrict__ bqa,
                          float* __restrict__ b1)
{
    __shared__ float part[4][HG];
    const int j = threadIdx.x & 63;
    const int p = threadIdx.x >> 6;
    float s = 0.f;
    for (int i = p * 256; i < (p + 1) * 256; ++i)
        s = fmaf(bq[i], Wqa[(size_t)i * HG + j], s);
    part[p][j] = s;
    __syncthreads();
    if (p == 0)
        b1[j] = bqa[j] + ((part[0][j] + part[1][j]) + (part[2][j] + part[3][j]));
}

__global__ __launch_bounds__(256) void zero_misc(
    float* __restrict__ gq, float* __restrict__ gk,
    float* __restrict__ cs, uint32_t* __restrict__ pad)
{
    const int i = blockIdx.x * 256 + threadIdx.x;
    gq[i] = 0.f; gk[i] = 0.f; pad[i] = 0u;
    if (i < BATCH * HG) cs[i] = 0.f;
}

__global__ __launch_bounds__(256) void sum_cols(
    const float* __restrict__ s, float* __restrict__ cs)
{
    const int b  = blockIdx.x;
    const int n0 = blockIdx.y * 256;
    const int c  = threadIdx.x & 63;
    const int rq = threadIdx.x >> 6;
    const float* base = s + ((size_t)b * SEQ + n0) * HG;
    float acc = 0.f;
    for (int n = rq; n < 256; n += 4)
        acc += base[(size_t)n * HG + c];
    __shared__ float part[4][HG];
    part[rq][c] = acc;
    __syncthreads();
    if (rq == 0)
        atomicAdd(&cs[b * HG + c],
                  (part[0][c] + part[1][c]) + (part[2][c] + part[3][c]));
}

__global__ __launch_bounds__(256) void gsum_h(
    const __half* __restrict__ x, const float* __restrict__ w,
    float* __restrict__ out)
{
    const int b = blockIdx.x / NH;
    const int h = blockIdx.x % NH;
    const int n0 = blockIdx.y * 256;
    const int g = threadIdx.x >> 6;
    const int d = threadIdx.x & 63;
    const __half* xp = x + ((size_t)b * SEQ + n0) * DM + h * HD + d;
    const float* wp = w + ((size_t)b * SEQ + n0) * HG + h * NG + g;
    float a0 = 0.f, a1 = 0.f, a2 = 0.f, a3 = 0.f;
    #pragma unroll 4
    for (int n = 0; n < 256; n += 4) {
        a0 = fmaf(__half2float(xp[(size_t)(n + 0) * DM]), wp[(size_t)(n + 0) * HG], a0);
        a1 = fmaf(__half2float(xp[(size_t)(n + 1) * DM]), wp[(size_t)(n + 1) * HG], a1);
        a2 = fmaf(__half2float(xp[(size_t)(n + 2) * DM]), wp[(size_t)(n + 2) * HG], a2);
        a3 = fmaf(__half2float(xp[(size_t)(n + 3) * DM]), wp[(size_t)(n + 3) * HG], a3);
    }
    atomicAdd(&out[(((size_t)(b * NH + h) * HD) + d) * NG + g],
              (a0 + a1) + (a2 + a3));
}

// ---------------------------------------------------------------------------
// Launch
// ---------------------------------------------------------------------------
extern "C" void kernel_launch(void* const* d_in, const int* in_sizes, int n_in,
                              void* d_out, int out_size)
{
    const float* hs   = (const float*)d_in[0];
    const float* mask = (const float*)d_in[1];
    const float* Wq   = (const float*)d_in[2];
    const float* bq   = (const float*)d_in[3];
    const float* Wqa  = (const float*)d_in[4];
    const float* bqa  = (const float*)d_in[5];
    const float* Wk   = (const float*)d_in[6];
    const float* bk   = (const float*)d_in[7];
    const float* Wka  = (const float*)d_in[8];
    const float* bka  = (const float*)d_in[9];
    const float* Wv   = (const float*)d_in[10];
    const float* bv   = (const float*)d_in[11];
    const float* Wt   = (const float*)d_in[12];
    const float* bt   = (const float*)d_in[13];
    float* out = (float*)d_out;

    float *s1, *s2, *gq, *gk, *cs, *b1, *zv;
    __half2 *gmm1, *gmm2;
    __half *qh, *kh, *vh, *ah, *wcat, *wt, *ws2;
    cudaGetSymbolAddress((void**)&s1,   g_s1);
    cudaGetSymbolAddress((void**)&s2,   g_s2);
    cudaGetSymbolAddress((void**)&gq,   g_gq);
    cudaGetSymbolAddress((void**)&gk,   g_gk);
    cudaGetSymbolAddress((void**)&cs,   g_cs);
    cudaGetSymbolAddress((void**)&b1,   g_b1);
    cudaGetSymbolAddress((void**)&zv,   g_zero);
    cudaGetSymbolAddress((void**)&gmm1, g_gmm1);
    cudaGetSymbolAddress((void**)&gmm2, g_gmm2);
    cudaGetSymbolAddress((void**)&qh,   g_qh);
    cudaGetSymbolAddress((void**)&kh,   g_kh);
    cudaGetSymbolAddress((void**)&vh,   g_vh);
    cudaGetSymbolAddress((void**)&ah,   g_ah);
    cudaGetSymbolAddress((void**)&wcat, g_wcat);
    cudaGetSymbolAddress((void**)&wt,   g_wt);
    cudaGetSymbolAddress((void**)&ws2,  g_ws2);

    cudaFuncSetAttribute(gemm_qkvs,   cudaFuncAttributeMaxDynamicSharedMemorySize, SMEM_BIG);
    cudaFuncSetAttribute(gemm_hmma_f, cudaFuncAttributeMaxDynamicSharedMemorySize, SMEM_BIGF);
    cudaFuncSetAttribute(gemm_n64_f,  cudaFuncAttributeMaxDynamicSharedMemorySize, SMEM_N64F);

    const size_t WSZ = (size_t)DM * DM;
    __half* ws1 = wcat + 3 * WSZ;
    uint32_t* pad = (uint32_t*)(wcat + 3 * WSZ + 64 * DM);

    dim3 bW(32, 8);

    // --- prep ---
    zero_misc<<<GSZ / 256, 256>>>(gq, gk, cs, pad);
    wconv4<<<dim3(DM / 32, DM / 32, 4), bW>>>(Wq, Wk, Wv, Wt, wcat, wt);
    sgemm_small<<<dim3(1, DM / 64), 256>>>(Wq, Wqa, zv, s2);
    wconv_t<<<dim3(HG / 32, DM / 32), bW>>>(s2, ws1, HG);
    bias_comb<<<1, 256>>>(bq, Wqa, bqa, b1);
    wconv_t<<<dim3(HG / 32, DM / 32), bW>>>(Wka, ws2, HG);
    tofp16<<<(MROWS * DM / 4) / 256, 256>>>((const float4*)hs, (__half2*)ah);

    // --- fused q,k,v,s1 projection ---
    gemm_qkvs<<<dim3(25, MROWS / 128), 256, SMEM_BIG>>>(
        ah, wcat, bq, bk, bv, b1, mask, qh, kh, vh, s1);

    // --- q-attention: colsum, gsum(exp), (max,min) table ---
    sum_cols<<<dim3(BATCH, SEQ / 256), 256>>>(s1, cs);
    gsum_h<<<dim3(BATCH * NH, SEQ / 256), 256>>>(qh, s1, gq);
    gminmax<<<(GSZ / 4) / 256, 256>>>(gq, cs, gmm1);

    // --- ksc (fused qk from kh+gmm1) -> gk -> (max,min) table ---
    gemm_n64_f<<<MROWS / 128, 256, SMEM_N64F>>>(kh, gmm1, ws2, bka, mask, s2);
    gsum_h<<<dim3(BATCH * NH, SEQ / 256), 256>>>(kh, s2, gk);
    gminmax<<<(GSZ / 4) / 256, 256>>>(gk, nullptr, gmm2);

    // --- out = (fused u from vh+gmm2) @ Wt + bt + qh ---
    gemm_hmma_f<<<dim3(DM / 128, MROWS / 128), 256, SMEM_BIGF>>>(
        vh, gmm2, wt, bt, qh, out);
}